// round 6
// baseline (speedup 1.0000x reference)
#include <cuda_runtime.h>
#include <cuda_bf16.h>
#include <cuda_fp16.h>
#include <math.h>
#include <stdint.h>

// ---------------- problem constants ----------------
#define BSZ   8192
#define LH    20
#define NFEAT 172
#define DIM   860
#define DHEAD 430
#define NHEAD 2
#define QKVN  2580
#define NROWS (BSZ*LH)      // 163840
#define LEF   688
#define KP2   704           // reduced K (no anony block) padded: 11*64
#define NC    (KP2/64)      // 11 k-chunks
#define NPAD2 2688          // 21*128

// ---------------- scratch ----------------
__device__ __half g_a[(size_t)NROWS * KP2];        // fp16 activations (no anony block)
__device__ __half g_b[(size_t)NPAD2 * KP2];        // fp16 weights
__device__ float g_aq [(size_t)(LH + 1) * QKVN];   // anony_emb @ W_anony^T (fp32 exact)
__device__ __half g_qkv[(size_t)NROWS * QKVN];     // fp16 qkv
__device__ float g_cm [(size_t)BSZ * DIM];
__device__ float g_m  [(size_t)BSZ * DIM];
__device__ float g_x  [(size_t)BSZ * DIM];
__device__ float g_h  [(size_t)BSZ * NFEAT];

// ---------------- helpers ----------------
__device__ __forceinline__ uint32_t smem_u32(const void* p) {
    uint32_t a;
    asm("{ .reg .u64 t; cvta.to.shared.u64 t, %1; cvt.u32.u64 %0, t; }" : "=r"(a) : "l"(p));
    return a;
}
__device__ __forceinline__ void cpa16(uint32_t s, const void* g) {
    asm volatile("cp.async.cg.shared.global [%0], [%1], 16;" :: "r"(s), "l"(g));
}
#define CP_COMMIT() asm volatile("cp.async.commit_group;" ::: "memory")
#define CP_WAIT2()  asm volatile("cp.async.wait_group 2;" ::: "memory")

#define LDSM4(r, addr) \
    asm volatile("ldmatrix.sync.aligned.m8n8.x4.shared.b16 {%0,%1,%2,%3}, [%4];" \
        : "=r"((r)[0]), "=r"((r)[1]), "=r"((r)[2]), "=r"((r)[3]) : "r"(addr) : "memory")
#define MMA_F16(acc, a, b0, b1) \
    asm volatile("mma.sync.aligned.m16n8k16.row.col.f32.f16.f16.f32 " \
        "{%0,%1,%2,%3}, {%4,%5,%6,%7}, {%8,%9}, {%0,%1,%2,%3};" \
        : "+f"((acc)[0]), "+f"((acc)[1]), "+f"((acc)[2]), "+f"((acc)[3]) \
        : "r"((a)[0]), "r"((a)[1]), "r"((a)[2]), "r"((a)[3]), "r"(b0), "r"(b1))

__device__ __forceinline__ float cos_accurate(float x) {
    double xd = (double)x;
    double q  = rint(xd * 0.15915494309189535);
    double r  = fma(q, -6.283185307179586476925286766559, xd);
    return cosf((float)r);
}
__device__ __forceinline__ unsigned long long pack2(float lo, float hi) {
    unsigned long long r;
    asm("mov.b64 %0, {%1, %2};" : "=l"(r) : "f"(lo), "f"(hi));
    return r;
}
__device__ __forceinline__ void fma2(unsigned long long& d, unsigned long long a, unsigned long long b) {
    asm("fma.rn.f32x2 %0, %1, %2, %3;" : "=l"(d) : "l"(a), "l"(b), "l"(d));
}
__device__ __forceinline__ float2 unpack2(unsigned long long v) {
    float2 f;
    asm("mov.b64 {%0, %1}, %2;" : "=f"(f.x), "=f"(f.y) : "l"(v));
    return f;
}

// ---------------- K1: gather + time-encode -> fp16 A (no anony block) ----------------
// K layout: [0,172) src | [172,344) dst | [344,516) edge | [516,688) ts | [688,704) pad
__global__ void build_full_kernel(
    const int* __restrict__ nids, const int* __restrict__ hist_nids,
    const int* __restrict__ anon_ids, const int* __restrict__ hist_eids,
    const float* __restrict__ hist_ts, const int* __restrict__ hist_dirs,
    const float* __restrict__ node_emb, const float* __restrict__ edge_emb,
    const float* __restrict__ anony_emb, const float* __restrict__ time_w,
    const float* __restrict__ time_b, float* __restrict__ out_prevts)
{
    int row = blockIdx.x;
    int b = row / LH;
    int l = row - b * LH;
    int nid = nids[b];
    int hn  = hist_nids[row];
    int d   = hist_dirs[row];
    int src = d ? nid : hn;
    int dst = d ? hn  : nid;
    int aid = anon_ids[row];
    int eid = hist_eids[row];
    float tlast = hist_ts[b * LH + (LH - 1)];
    float dt = __fsub_rn(tlast, hist_ts[row]);
    bool last = (l == LH - 1);

    for (int j = threadIdx.x; j < KP2; j += blockDim.x) {
        float val = 0.0f;
        if (j < 172)      val = node_emb[(size_t)src * NFEAT + j];
        else if (j < 344) val = node_emb[(size_t)dst * NFEAT + (j - 172)];
        else if (j < 516) val = edge_emb[(size_t)eid * NFEAT + (j - 344)];
        else if (j < 688) {
            int jj = j - 516;
            float x = __fmul_rn(dt, time_w[jj]);
            x = __fadd_rn(x, time_b[jj]);
            val = cos_accurate(x);
        }
        if (last && j < 516) {
            // last_event_feat (original order: src, dst, anony, edge)
            int xo = (j < 344) ? (NFEAT + j) : (NFEAT + j + NFEAT);  // edge shifts past anony
            g_x[(size_t)b * DIM + xo] = val;
            val = 0.0f;
        }
        g_a[(size_t)row * KP2 + j] = __float2half_rn(val);
    }
    if (last) {
        for (int j = threadIdx.x; j < NFEAT; j += blockDim.x)
            g_x[(size_t)b * DIM + NFEAT + 344 + j] = anony_emb[(size_t)aid * NFEAT + j];
        if (threadIdx.x == 0) out_prevts[b] = tlast;
    }
}

// ---------------- K1b: in_proj_w (minus anony cols) -> padded fp16 ----------------
__global__ void split_b_kernel(const float* __restrict__ W)
{
    size_t idx = (size_t)blockIdx.x * blockDim.x + threadIdx.x;
    if (idx >= (size_t)NPAD2 * KP2) return;
    int r = (int)(idx / KP2);
    int k = (int)(idx - (size_t)r * KP2);
    float v = 0.0f;
    if (r < QKVN) {
        if (k < 344)      v = W[(size_t)r * DIM + k];
        else if (k < 688) v = W[(size_t)r * DIM + k + NFEAT];   // skip anony cols [344,516)
    }
    g_b[idx] = __float2half_rn(v);
}

// ---------------- K1c: AQ = anony_emb @ W[:,344:516]^T  (21 x 2580, fp32 exact) ----------------
__global__ void anony_proj_kernel(const float* __restrict__ anony_emb,
                                  const float* __restrict__ W)
{
    int n = blockIdx.x * blockDim.x + threadIdx.x;
    int a = blockIdx.y;
    if (n >= QKVN) return;
    float s = 0.0f;
    const float* wr = W + (size_t)n * DIM + 344;
    const float* ar = anony_emb + (size_t)a * NFEAT;
    #pragma unroll 4
    for (int k = 0; k < NFEAT; k++) s += ar[k] * wr[k];
    g_aq[(size_t)a * QKVN + n] = s;
}

// ---------------- K2: qkv GEMM via fp16 mma.sync ----------------
// CTA tile 256x128, 8 warps of 64x64, BK=64, 4-stage cp.async pipeline.
// stage: A 256x128B = 32KB at +0, B 128x128B = 16KB at +32768. 48KB/stage, 192KB total.
#define QSM_STAGE 49152
#define QSM_TOTAL (4*QSM_STAGE)

__device__ __forceinline__ void qkv_load_stage(
    uint32_t sb, int stage, int c, int bm, int bn, int tid,
    const __half* A, const __half* B)
{
    uint32_t sbase = sb + stage * QSM_STAGE;
    const size_t kof = (size_t)c * 64;
    // A: 256 rows x 128B
    #pragma unroll
    for (int it = 0; it < 8; it++) {
        int cid = tid + it * 256;          // 0..2047
        int r  = cid >> 3;
        int kc = cid & 7;
        uint32_t soff = (uint32_t)(r * 128 + ((kc ^ (r & 7)) << 4));
        const char* ga = (const char*)(A + (size_t)(bm + r) * KP2 + kof) + kc * 16;
        cpa16(sbase + soff, ga);
    }
    // B: 128 rows x 128B
    #pragma unroll
    for (int it = 0; it < 4; it++) {
        int cid = tid + it * 256;          // 0..1023
        int r  = cid >> 3;
        int kc = cid & 7;
        uint32_t soff = (uint32_t)(r * 128 + ((kc ^ (r & 7)) << 4));
        const char* gb = (const char*)(B + (size_t)(bn + r) * KP2 + kof) + kc * 16;
        cpa16(sbase + 32768 + soff, gb);
    }
    CP_COMMIT();
}

__global__ __launch_bounds__(256, 1) void qkv_mma_kernel(
    const __half* __restrict__ A, const __half* __restrict__ B,
    const float* __restrict__ bias, const float* __restrict__ AQ,
    const int* __restrict__ anon_ids, __half* __restrict__ C)
{
    extern __shared__ char smem[];
    const uint32_t sb = smem_u32(smem);
    const int tid = threadIdx.x;
    const int wid = tid >> 5;
    const int lane = tid & 31;
    const int warp_m = wid >> 1;       // 0..3 -> 64 rows each
    const int warp_n = wid & 1;        // 0..1 -> 64 cols each
    const int bm = blockIdx.y * 256;
    const int bn = blockIdx.x * 128;

    float acc[4][8][4];
    #pragma unroll
    for (int mi = 0; mi < 4; mi++)
        #pragma unroll
        for (int nf = 0; nf < 8; nf++)
            #pragma unroll
            for (int t = 0; t < 4; t++) acc[mi][nf][t] = 0.0f;

    qkv_load_stage(sb, 0, 0, bm, bn, tid, A, B);
    qkv_load_stage(sb, 1, 1, bm, bn, tid, A, B);
    qkv_load_stage(sb, 2, 2, bm, bn, tid, A, B);

    for (int c = 0; c < NC; c++) {
        const int stage = c & 3;
        CP_WAIT2();
        __syncthreads();
        if (c + 3 < NC)
            qkv_load_stage(sb, (c + 3) & 3, c + 3, bm, bn, tid, A, B);

        const uint32_t sA = sb + stage * QSM_STAGE;
        const uint32_t sB = sA + 32768;
        #pragma unroll
        for (int kk = 0; kk < 4; kk++) {
            uint32_t ah[4][4];
            #pragma unroll
            for (int mi = 0; mi < 4; mi++) {
                int mrow = warp_m * 64 + mi * 16 + (lane & 15);
                int chunk = kk * 2 + (lane >> 4);
                uint32_t addr = sA + mrow * 128 + ((chunk ^ (mrow & 7)) << 4);
                LDSM4(ah[mi], addr);
            }
            // B: NON-trans ldmatrix on [n][k] row-major smem; 4 np blocks cover 64 cols.
            uint32_t bh[4][4];
            #pragma unroll
            for (int np = 0; np < 4; np++) {
                int nrow = warp_n * 64 + np * 16 + ((lane >> 4) << 3) + (lane & 7);
                int chunk = kk * 2 + ((lane >> 3) & 1);
                uint32_t addr = sB + nrow * 128 + ((chunk ^ (nrow & 7)) << 4);
                LDSM4(bh[np], addr);
            }
            #pragma unroll
            for (int mi = 0; mi < 4; mi++) {
                #pragma unroll
                for (int nf = 0; nf < 8; nf++) {
                    int np = nf >> 1, ri = (nf & 1) * 2;
                    MMA_F16(acc[mi][nf], ah[mi], bh[np][ri], bh[np][ri + 1]);
                }
            }
        }
    }

    // epilogue: + bias + anony gather (zero for last row of each sequence); fp16 out
    const int group = lane >> 2;
    const int tc2 = (lane & 3) * 2;
    #pragma unroll
    for (int mi = 0; mi < 4; mi++) {
        int r0 = bm + warp_m * 64 + mi * 16 + group;
        int r1 = r0 + 8;
        int aid0 = anon_ids[r0];
        int aid1 = anon_ids[r1];
        bool nl0 = (r0 % LH) != (LH - 1);
        bool nl1 = (r1 % LH) != (LH - 1);
        #pragma unroll
        for (int nf = 0; nf < 8; nf++) {
            int n = bn + warp_n * 64 + nf * 8 + tc2;
            if (n >= QKVN) continue;
            float2 bv = *(const float2*)(bias + n);
            float2 o0, o1;
            o0.x = acc[mi][nf][0] + bv.x;
            o0.y = acc[mi][nf][1] + bv.y;
            o1.x = acc[mi][nf][2] + bv.x;
            o1.y = acc[mi][nf][3] + bv.y;
            if (nl0) {
                float2 q = *(const float2*)(AQ + (size_t)aid0 * QKVN + n);
                o0.x += q.x; o0.y += q.y;
            }
            if (nl1) {
                float2 q = *(const float2*)(AQ + (size_t)aid1 * QKVN + n);
                o1.x += q.x; o1.y += q.y;
            }
            *(__half2*)(C + (size_t)r0 * QKVN + n) = __floats2half2_rn(o0.x, o0.y);
            *(__half2*)(C + (size_t)r1 * QKVN + n) = __floats2half2_rn(o1.x, o1.y);
        }
    }
}

// ---------------- small-GEMM path (f32x2 SIMT) for K4-K7 ----------------
#define GBM 128
#define GBN 64
#define GBK 16

template<bool RELU_A, bool RELU_C>
__global__ __launch_bounds__(256) void gemm_nt(
    const float* __restrict__ A, int lda,
    const float* __restrict__ B, int ldb,
    const float* __restrict__ bias,
    float* __restrict__ C, int ldc,
    float* __restrict__ C2, int ldc2,
    int M, int N, int K)
{
    __shared__ float As[GBK][GBM + 4];
    __shared__ float Bs[GBK][GBN + 4];
    const int tid = threadIdx.x;
    const int tx = tid & 15;
    const int ty = tid >> 4;
    const int bm = blockIdx.y * GBM;
    const int bn = blockIdx.x * GBN;

    unsigned long long acc[4][4];
    #pragma unroll
    for (int p = 0; p < 4; p++)
        #pragma unroll
        for (int j = 0; j < 4; j++) acc[p][j] = 0ull;

    const int lr = tid >> 2;
    const int lc = (tid & 3) * 4;

    for (int k0 = 0; k0 < K; k0 += GBK) {
        #pragma unroll
        for (int r = 0; r < 2; r++) {
            int mrow = bm + lr + r * 64;
            float4 v = make_float4(0.f, 0.f, 0.f, 0.f);
            if (mrow < M && (k0 + lc) < K)
                v = *reinterpret_cast<const float4*>(A + (size_t)mrow * lda + k0 + lc);
            if (RELU_A) {
                v.x = fmaxf(v.x, 0.f); v.y = fmaxf(v.y, 0.f);
                v.z = fmaxf(v.z, 0.f); v.w = fmaxf(v.w, 0.f);
            }
            As[lc + 0][lr + r * 64] = v.x; As[lc + 1][lr + r * 64] = v.y;
            As[lc + 2][lr + r * 64] = v.z; As[lc + 3][lr + r * 64] = v.w;
        }
        {
            int nrow = bn + lr;
            float4 v = make_float4(0.f, 0.f, 0.f, 0.f);
            if (nrow < N && (k0 + lc) < K)
                v = *reinterpret_cast<const float4*>(B + (size_t)nrow * ldb + k0 + lc);
            Bs[lc + 0][lr] = v.x; Bs[lc + 1][lr] = v.y;
            Bs[lc + 2][lr] = v.z; Bs[lc + 3][lr] = v.w;
        }
        __syncthreads();
        #pragma unroll
        for (int kk = 0; kk < GBK; kk++) {
            const unsigned long long* ap =
                reinterpret_cast<const unsigned long long*>(&As[kk][ty * 8]);
            unsigned long long a0 = ap[0], a1 = ap[1], a2 = ap[2], a3 = ap[3];
            const float4 bq = *reinterpret_cast<const float4*>(&Bs[kk][tx * 4]);
            unsigned long long b0 = pack2(bq.x, bq.x), b1 = pack2(bq.y, bq.y);
            unsigned long long b2 = pack2(bq.z, bq.z), b3 = pack2(bq.w, bq.w);
            fma2(acc[0][0], a0, b0); fma2(acc[0][1], a0, b1); fma2(acc[0][2], a0, b2); fma2(acc[0][3], a0, b3);
            fma2(acc[1][0], a1, b0); fma2(acc[1][1], a1, b1); fma2(acc[1][2], a1, b2); fma2(acc[1][3], a1, b3);
            fma2(acc[2][0], a2, b0); fma2(acc[2][1], a2, b1); fma2(acc[2][2], a2, b2); fma2(acc[2][3], a2, b3);
            fma2(acc[3][0], a3, b0); fma2(acc[3][1], a3, b1); fma2(acc[3][2], a3, b2); fma2(acc[3][3], a3, b3);
        }
        __syncthreads();
    }

    #pragma unroll
    for (int j = 0; j < 4; j++) {
        int n = bn + tx * 4 + j;
        if (n >= N) continue;
        float bv = bias[n];
        #pragma unroll
        for (int p = 0; p < 4; p++) {
            float2 cc = unpack2(acc[p][j]);
            int m0 = bm + ty * 8 + 2 * p;
            float lo = cc.x + bv, hi = cc.y + bv;
            if (RELU_C) { lo = fmaxf(lo, 0.f); hi = fmaxf(hi, 0.f); }
            if (m0 < M) {
                C[(size_t)m0 * ldc + n] = lo;
                if (C2) C2[(size_t)m0 * ldc2 + n] = lo;
            }
            if (m0 + 1 < M) {
                C[(size_t)(m0 + 1) * ldc + n] = hi;
                if (C2) C2[(size_t)(m0 + 1) * ldc2 + n] = hi;
            }
        }
    }
}

// ---------------- K3: attention per (b, head) -> query-mean of ctx ----------------
#define SSTR 448
#define ATT_SMEM ((3*LH*SSTR + LH*LH + LH + 4) * 4)

__global__ __launch_bounds__(256) void attn_mean_kernel(
    const __half* __restrict__ qkv, const int* __restrict__ hist_nids,
    float* __restrict__ ctx_mean)
{
    extern __shared__ float sm[];
    float* sq = sm;
    float* sk = sq + LH * SSTR;
    float* sv = sk + LH * SSTR;
    float* sc = sv + LH * SSTR;
    float* wb = sc + LH * LH;

    int b = blockIdx.x;
    int h = blockIdx.y;
    int tid = threadIdx.x;
    const float scale = (float)(1.0 / sqrt(430.0));

    size_t base = (size_t)b * LH * QKVN + (size_t)h * DHEAD;
    // half2 loads: SSTR/2 = 224 pairs per row
    for (int idx = tid; idx < LH * (SSTR / 2); idx += 256) {
        int l = idx / (SSTR / 2), dp = idx - l * (SSTR / 2);
        int dd = dp * 2;
        float qx = 0.f, qy = 0.f, kx = 0.f, ky = 0.f, vx = 0.f, vy = 0.f;
        if (dd < DHEAD) {
            size_t o = base + (size_t)l * QKVN + dd;
            float2 qq = __half22float2(*(const __half2*)(qkv + o));
            float2 kk = __half22float2(*(const __half2*)(qkv + o + DIM));
            float2 vv = __half22float2(*(const __half2*)(qkv + o + 2 * DIM));
            qx = qq.x; qy = qq.y; kx = kk.x; ky = kk.y; vx = vv.x; vy = vv.y;
        }
        sq[l * SSTR + dd] = qx; sq[l * SSTR + dd + 1] = qy;
        sk[l * SSTR + dd] = kx; sk[l * SSTR + dd + 1] = ky;
        sv[l * SSTR + dd] = vx; sv[l * SSTR + dd + 1] = vy;
    }
    __syncthreads();

    int w = tid >> 5, lane = tid & 31;
    for (int qi = w; qi < LH; qi += 8) {
        float qreg[14];
        #pragma unroll
        for (int t = 0; t < 14; t++) qreg[t] = sq[qi * SSTR + lane + 32 * t];
        for (int ki = 0; ki < LH; ki++) {
            float s = 0.f;
            #pragma unroll
            for (int t = 0; t < 14; t++) s += qreg[t] * sk[ki * SSTR + lane + 32 * t];
            #pragma unroll
            for (int off = 16; off > 0; off >>= 1) s += __shfl_xor_sync(0xffffffffu, s, off);
            if (lane == 0) {
                int hn = hist_nids[b * LH + ki];
                bool masked = (hn == 0) && (ki != LH - 1);
                sc[qi * LH + ki] = masked ? -1e30f : s * scale;
            }
        }
    }
    __syncthreads();

    if (tid < LH) {
        int qi = tid;
        float mx = -1e30f;
        for (int ki = 0; ki < LH; ki++) mx = fmaxf(mx, sc[qi * LH + ki]);
        float sum = 0.f;
        for (int ki = 0; ki < LH; ki++) {
            float e = expf(sc[qi * LH + ki] - mx);
            sc[qi * LH + ki] = e;
            sum += e;
        }
        float inv = 1.f / sum;
        for (int ki = 0; ki < LH; ki++) sc[qi * LH + ki] *= inv;
    }
    __syncthreads();

    if (tid < LH) {
        int ki = tid;
        float s = 0.f;
        for (int qi = 0; qi < LH; qi++) s += sc[qi * LH + ki];
        wb[ki] = s * (1.0f / LH);
    }
    __syncthreads();

    for (int dd = tid; dd < DHEAD; dd += 256) {
        float s = 0.f;
        #pragma unroll
        for (int ki = 0; ki < LH; ki++) s += wb[ki] * sv[ki * SSTR + dd];
        ctx_mean[(size_t)b * DIM + (size_t)h * DHEAD + dd] = s;
    }
}

// ---------------- host ----------------
extern "C" void kernel_launch(void* const* d_in, const int* in_sizes, int n_in,
                              void* d_out, int out_size)
{
    const int*   nids       = (const int*)  d_in[0];
    const int*   hist_nids  = (const int*)  d_in[1];
    const int*   anon_ids   = (const int*)  d_in[2];
    const int*   hist_eids  = (const int*)  d_in[3];
    const float* hist_ts    = (const float*)d_in[4];
    const int*   hist_dirs  = (const int*)  d_in[5];
    const float* node_emb   = (const float*)d_in[6];
    const float* edge_emb   = (const float*)d_in[7];
    const float* anony_emb  = (const float*)d_in[8];
    const float* time_w     = (const float*)d_in[9];
    const float* time_b     = (const float*)d_in[10];
    const float* in_proj_w  = (const float*)d_in[11];
    const float* in_proj_b  = (const float*)d_in[12];
    const float* out_proj_w = (const float*)d_in[13];
    const float* out_proj_b = (const float*)d_in[14];
    const float* outfn_w    = (const float*)d_in[15];
    const float* outfn_b    = (const float*)d_in[16];
    const float* fc1_w      = (const float*)d_in[17];
    const float* fc1_b      = (const float*)d_in[18];
    const float* fc2_w      = (const float*)d_in[19];
    const float* fc2_b      = (const float*)d_in[20];

    float* out     = (float*)d_out;
    float* out_hl  = out;
    float* out_hr  = out + (size_t)BSZ * NFEAT;
    float* out_pts = out + (size_t)2 * BSZ * NFEAT;

    __half *a16, *b16, *qkv;
    float *aq, *cm, *mbuf, *xbuf, *hbuf;
    cudaGetSymbolAddress((void**)&a16, g_a);
    cudaGetSymbolAddress((void**)&b16, g_b);
    cudaGetSymbolAddress((void**)&aq,  g_aq);
    cudaGetSymbolAddress((void**)&qkv, g_qkv);
    cudaGetSymbolAddress((void**)&cm,  g_cm);
    cudaGetSymbolAddress((void**)&mbuf, g_m);
    cudaGetSymbolAddress((void**)&xbuf, g_x);
    cudaGetSymbolAddress((void**)&hbuf, g_h);

    cudaFuncSetAttribute(attn_mean_kernel,
                         cudaFuncAttributeMaxDynamicSharedMemorySize, ATT_SMEM);
    cudaFuncSetAttribute(qkv_mma_kernel,
                         cudaFuncAttributeMaxDynamicSharedMemorySize, QSM_TOTAL);

    // K1 family: build operands
    build_full_kernel<<<NROWS, 128>>>(nids, hist_nids, anon_ids, hist_eids, hist_ts,
                                      hist_dirs, node_emb, edge_emb, anony_emb,
                                      time_w, time_b, out_pts);
    {
        size_t tot = (size_t)NPAD2 * KP2;
        split_b_kernel<<<(int)((tot + 255) / 256), 256>>>(in_proj_w);
    }
    anony_proj_kernel<<<dim3((QKVN + 255) / 256, LH + 1), 256>>>(anony_emb, in_proj_w);

    // K2: qkv GEMM, fp16 mma.sync, 256x128 CTA tile
    {
        dim3 grid(NPAD2 / 128, NROWS / 256);
        qkv_mma_kernel<<<grid, 256, QSM_TOTAL>>>(a16, b16, in_proj_b, aq, anon_ids, qkv);
    }

    // K3: attention -> ctx mean over L
    attn_mean_kernel<<<dim3(BSZ, NHEAD), 256, ATT_SMEM>>>(qkv, hist_nids, cm);

    // K4: m = ctx_mean @ out_proj_w^T + b
    {
        dim3 grid((DIM + GBN - 1) / GBN, BSZ / GBM);
        gemm_nt<false, false><<<grid, 256>>>(cm, DIM, out_proj_w, DIM, out_proj_b,
                                             mbuf, DIM, (float*)nullptr, 0,
                                             BSZ, DIM, DIM);
    }
    // K5: hl = relu(m) @ outfn_w^T + b -> d_out AND x[:, :172]
    {
        dim3 grid((NFEAT + GBN - 1) / GBN, BSZ / GBM);
        gemm_nt<true, false><<<grid, 256>>>(mbuf, DIM, outfn_w, DIM, outfn_b,
                                            out_hl, NFEAT, xbuf, DIM,
                                            BSZ, NFEAT, DIM);
    }
    // K6: h = relu(x @ fc1_w^T + b)
    {
        dim3 grid((NFEAT + GBN - 1) / GBN, BSZ / GBM);
        gemm_nt<false, true><<<grid, 256>>>(xbuf, DIM, fc1_w, DIM, fc1_b,
                                            hbuf, NFEAT, (float*)nullptr, 0,
                                            BSZ, NFEAT, DIM);
    }
    // K7: hr = h @ fc2_w^T + b -> d_out
    {
        dim3 grid((NFEAT + GBN - 1) / GBN, BSZ / GBM);
        gemm_nt<false, false><<<grid, 256>>>(hbuf, NFEAT, fc2_w, NFEAT, fc2_b,
                                             out_hr, NFEAT, (float*)nullptr, 0,
                                             BSZ, NFEAT, NFEAT);
    }
}

// round 7
// speedup vs baseline: 1.1481x; 1.1481x over previous
#include <cuda_runtime.h>
#include <cuda_bf16.h>
#include <cuda_fp16.h>
#include <math.h>
#include <stdint.h>

// ---------------- problem constants ----------------
#define BSZ   8192
#define LH    20
#define NFEAT 172
#define DIM   860
#define DHEAD 430
#define NHEAD 2
#define QKVN  2580
#define NROWS (BSZ*LH)      // 163840
#define LEF   688
#define KP2   704           // reduced K (no anony block) padded: 11*64
#define NC    (KP2/64)      // 11 k-chunks
#define NPAD2 2688          // 21*128

// ---------------- scratch ----------------
__device__ __half g_a[(size_t)NROWS * KP2];        // fp16 activations (no anony block)
__device__ __half g_b[(size_t)NPAD2 * KP2];        // fp16 weights
__device__ float g_aq [(size_t)(LH + 1) * QKVN];   // anony_emb @ W_anony^T (fp32 exact)
__device__ __half g_qkv[(size_t)NROWS * QKVN];     // fp16 qkv
__device__ float g_cm [(size_t)BSZ * DIM];
__device__ float g_m  [(size_t)BSZ * DIM];
__device__ float g_x  [(size_t)BSZ * DIM];
__device__ float g_h  [(size_t)BSZ * NFEAT];

// ---------------- helpers ----------------
__device__ __forceinline__ uint32_t smem_u32(const void* p) {
    uint32_t a;
    asm("{ .reg .u64 t; cvta.to.shared.u64 t, %1; cvt.u32.u64 %0, t; }" : "=r"(a) : "l"(p));
    return a;
}
__device__ __forceinline__ void cpa16(uint32_t s, const void* g) {
    asm volatile("cp.async.cg.shared.global [%0], [%1], 16;" :: "r"(s), "l"(g));
}
#define CP_COMMIT() asm volatile("cp.async.commit_group;" ::: "memory")
#define CP_WAIT1()  asm volatile("cp.async.wait_group 1;" ::: "memory")

#define LDSM4(r, addr) \
    asm volatile("ldmatrix.sync.aligned.m8n8.x4.shared.b16 {%0,%1,%2,%3}, [%4];" \
        : "=r"((r)[0]), "=r"((r)[1]), "=r"((r)[2]), "=r"((r)[3]) : "r"(addr) : "memory")
#define MMA_F16(acc, a, b0, b1) \
    asm volatile("mma.sync.aligned.m16n8k16.row.col.f32.f16.f16.f32 " \
        "{%0,%1,%2,%3}, {%4,%5,%6,%7}, {%8,%9}, {%0,%1,%2,%3};" \
        : "+f"((acc)[0]), "+f"((acc)[1]), "+f"((acc)[2]), "+f"((acc)[3]) \
        : "r"((a)[0]), "r"((a)[1]), "r"((a)[2]), "r"((a)[3]), "r"(b0), "r"(b1))

__device__ __forceinline__ float cos_accurate(float x) {
    double xd = (double)x;
    double q  = rint(xd * 0.15915494309189535);
    double r  = fma(q, -6.283185307179586476925286766559, xd);
    return cosf((float)r);
}
__device__ __forceinline__ unsigned long long pack2(float lo, float hi) {
    unsigned long long r;
    asm("mov.b64 %0, {%1, %2};" : "=l"(r) : "f"(lo), "f"(hi));
    return r;
}
__device__ __forceinline__ void fma2(unsigned long long& d, unsigned long long a, unsigned long long b) {
    asm("fma.rn.f32x2 %0, %1, %2, %3;" : "=l"(d) : "l"(a), "l"(b), "l"(d));
}
__device__ __forceinline__ float2 unpack2(unsigned long long v) {
    float2 f;
    asm("mov.b64 {%0, %1}, %2;" : "=f"(f.x), "=f"(f.y) : "l"(v));
    return f;
}

// ---------------- K1: gather + time-encode -> fp16 A (no anony block) ----------------
// K layout: [0,172) src | [172,344) dst | [344,516) edge | [516,688) ts | [688,704) pad
__global__ void build_full_kernel(
    const int* __restrict__ nids, const int* __restrict__ hist_nids,
    const int* __restrict__ anon_ids, const int* __restrict__ hist_eids,
    const float* __restrict__ hist_ts, const int* __restrict__ hist_dirs,
    const float* __restrict__ node_emb, const float* __restrict__ edge_emb,
    const float* __restrict__ anony_emb, const float* __restrict__ time_w,
    const float* __restrict__ time_b, float* __restrict__ out_prevts)
{
    int row = blockIdx.x;
    int b = row / LH;
    int l = row - b * LH;
    int nid = nids[b];
    int hn  = hist_nids[row];
    int d   = hist_dirs[row];
    int src = d ? nid : hn;
    int dst = d ? hn  : nid;
    int aid = anon_ids[row];
    int eid = hist_eids[row];
    float tlast = hist_ts[b * LH + (LH - 1)];
    float dt = __fsub_rn(tlast, hist_ts[row]);
    bool last = (l == LH - 1);

    for (int j = threadIdx.x; j < KP2; j += blockDim.x) {
        float val = 0.0f;
        if (j < 172)      val = node_emb[(size_t)src * NFEAT + j];
        else if (j < 344) val = node_emb[(size_t)dst * NFEAT + (j - 172)];
        else if (j < 516) val = edge_emb[(size_t)eid * NFEAT + (j - 344)];
        else if (j < 688) {
            int jj = j - 516;
            float x = __fmul_rn(dt, time_w[jj]);
            x = __fadd_rn(x, time_b[jj]);
            val = cos_accurate(x);
        }
        if (last && j < 516) {
            // last_event_feat (original order: src, dst, anony, edge)
            int xo = (j < 344) ? (NFEAT + j) : (NFEAT + j + NFEAT);  // edge shifts past anony
            g_x[(size_t)b * DIM + xo] = val;
            val = 0.0f;
        }
        g_a[(size_t)row * KP2 + j] = __float2half_rn(val);
    }
    if (last) {
        for (int j = threadIdx.x; j < NFEAT; j += blockDim.x)
            g_x[(size_t)b * DIM + NFEAT + 344 + j] = anony_emb[(size_t)aid * NFEAT + j];
        if (threadIdx.x == 0) out_prevts[b] = tlast;
    }
}

// ---------------- K1b: in_proj_w (minus anony cols) -> padded fp16 ----------------
__global__ void split_b_kernel(const float* __restrict__ W)
{
    size_t idx = (size_t)blockIdx.x * blockDim.x + threadIdx.x;
    if (idx >= (size_t)NPAD2 * KP2) return;
    int r = (int)(idx / KP2);
    int k = (int)(idx - (size_t)r * KP2);
    float v = 0.0f;
    if (r < QKVN) {
        if (k < 344)      v = W[(size_t)r * DIM + k];
        else if (k < 688) v = W[(size_t)r * DIM + k + NFEAT];   // skip anony cols [344,516)
    }
    g_b[idx] = __float2half_rn(v);
}

// ---------------- K1c: AQ = anony_emb @ W[:,344:516]^T  (21 x 2580, fp32 exact) ----------------
__global__ void anony_proj_kernel(const float* __restrict__ anony_emb,
                                  const float* __restrict__ W)
{
    int n = blockIdx.x * blockDim.x + threadIdx.x;
    int a = blockIdx.y;
    if (n >= QKVN) return;
    float s = 0.0f;
    const float* wr = W + (size_t)n * DIM + 344;
    const float* ar = anony_emb + (size_t)a * NFEAT;
    #pragma unroll 4
    for (int k = 0; k < NFEAT; k++) s += ar[k] * wr[k];
    g_aq[(size_t)a * QKVN + n] = s;
}

// ---------------- K2: qkv GEMM via single-term fp16 mma.sync ----------------
// CTA tile 128x128, BK=64, 3-stage cp.async pipeline, 32KB/stage -> 2 CTAs/SM. (R5 geometry)
#define QSM_STAGE 32768
#define QSM_TOTAL (3*QSM_STAGE)

__device__ __forceinline__ void qkv_load_stage(
    uint32_t sb, int stage, int c, int bm, int bn, int tid,
    const __half* A, const __half* B)
{
    uint32_t sbase = sb + stage * QSM_STAGE;
    const size_t kof = (size_t)c * 64;
    #pragma unroll
    for (int it = 0; it < 4; it++) {
        int cid = tid + it * 256;          // 0..1023
        int r  = cid >> 3;
        int kc = cid & 7;
        uint32_t soff = (uint32_t)(r * 128 + ((kc ^ (r & 7)) << 4));
        const char* ga = (const char*)(A + (size_t)(bm + r) * KP2 + kof) + kc * 16;
        const char* gb = (const char*)(B + (size_t)(bn + r) * KP2 + kof) + kc * 16;
        cpa16(sbase +         soff, ga);
        cpa16(sbase + 16384 + soff, gb);
    }
    CP_COMMIT();
}

__global__ __launch_bounds__(256, 2) void qkv_mma_kernel(
    const __half* __restrict__ A, const __half* __restrict__ B,
    const float* __restrict__ bias, const float* __restrict__ AQ,
    const int* __restrict__ anon_ids, __half* __restrict__ C)
{
    extern __shared__ char smem[];
    const uint32_t sb = smem_u32(smem);
    const int tid = threadIdx.x;
    const int wid = tid >> 5;
    const int lane = tid & 31;
    const int warp_m = wid >> 2;       // 0..1 -> 64 rows each
    const int warp_n = wid & 3;        // 0..3 -> 32 cols each
    const int bm = blockIdx.y * 128;
    const int bn = blockIdx.x * 128;

    float acc[4][4][4];
    #pragma unroll
    for (int mi = 0; mi < 4; mi++)
        #pragma unroll
        for (int nf = 0; nf < 4; nf++)
            #pragma unroll
            for (int t = 0; t < 4; t++) acc[mi][nf][t] = 0.0f;

    qkv_load_stage(sb, 0, 0, bm, bn, tid, A, B);
    qkv_load_stage(sb, 1, 1, bm, bn, tid, A, B);

    for (int c = 0; c < NC; c++) {
        const int stage = c % 3;
        CP_WAIT1();
        __syncthreads();
        if (c + 2 < NC)
            qkv_load_stage(sb, (c + 2) % 3, c + 2, bm, bn, tid, A, B);

        const uint32_t sA = sb + stage * QSM_STAGE;
        const uint32_t sB = sA + 16384;
        #pragma unroll
        for (int kk = 0; kk < 4; kk++) {
            uint32_t ah[4][4];
            #pragma unroll
            for (int mi = 0; mi < 4; mi++) {
                int mrow = warp_m * 64 + mi * 16 + (lane & 15);
                int chunk = kk * 2 + (lane >> 4);
                uint32_t addr = sA + mrow * 128 + ((chunk ^ (mrow & 7)) << 4);
                LDSM4(ah[mi], addr);
            }
            // B: NON-trans ldmatrix on [n][k] row-major smem.
            uint32_t bh[2][4];
            #pragma unroll
            for (int np = 0; np < 2; np++) {
                int nrow = warp_n * 32 + np * 16 + ((lane >> 4) << 3) + (lane & 7);
                int chunk = kk * 2 + ((lane >> 3) & 1);
                uint32_t addr = sB + nrow * 128 + ((chunk ^ (nrow & 7)) << 4);
                LDSM4(bh[np], addr);
            }
            #pragma unroll
            for (int mi = 0; mi < 4; mi++) {
                #pragma unroll
                for (int nf = 0; nf < 4; nf++) {
                    int np = nf >> 1, ri = (nf & 1) * 2;
                    MMA_F16(acc[mi][nf], ah[mi], bh[np][ri], bh[np][ri + 1]);
                }
            }
        }
    }

    // epilogue: + bias + anony gather (zero for last row of each sequence); fp16 out
    const int group = lane >> 2;
    const int tc2 = (lane & 3) * 2;
    #pragma unroll
    for (int mi = 0; mi < 4; mi++) {
        int r0 = bm + warp_m * 64 + mi * 16 + group;
        int r1 = r0 + 8;
        int aid0 = anon_ids[r0];
        int aid1 = anon_ids[r1];
        bool nl0 = (r0 % LH) != (LH - 1);
        bool nl1 = (r1 % LH) != (LH - 1);
        #pragma unroll
        for (int nf = 0; nf < 4; nf++) {
            int n = bn + warp_n * 32 + nf * 8 + tc2;
            if (n >= QKVN) continue;
            float2 bv = *(const float2*)(bias + n);
            float2 o0, o1;
            o0.x = acc[mi][nf][0] + bv.x;
            o0.y = acc[mi][nf][1] + bv.y;
            o1.x = acc[mi][nf][2] + bv.x;
            o1.y = acc[mi][nf][3] + bv.y;
            if (nl0) {
                float2 q = *(const float2*)(AQ + (size_t)aid0 * QKVN + n);
                o0.x += q.x; o0.y += q.y;
            }
            if (nl1) {
                float2 q = *(const float2*)(AQ + (size_t)aid1 * QKVN + n);
                o1.x += q.x; o1.y += q.y;
            }
            *(__half2*)(C + (size_t)r0 * QKVN + n) = __floats2half2_rn(o0.x, o0.y);
            *(__half2*)(C + (size_t)r1 * QKVN + n) = __floats2half2_rn(o1.x, o1.y);
        }
    }
}

// ---------------- small-GEMM path (f32x2 SIMT) for K4-K7 ----------------
#define GBM 128
#define GBN 64
#define GBK 16

template<bool RELU_A, bool RELU_C>
__global__ __launch_bounds__(256) void gemm_nt(
    const float* __restrict__ A, int lda,
    const float* __restrict__ B, int ldb,
    const float* __restrict__ bias,
    float* __restrict__ C, int ldc,
    float* __restrict__ C2, int ldc2,
    int M, int N, int K)
{
    __shared__ float As[GBK][GBM + 4];
    __shared__ float Bs[GBK][GBN + 4];
    const int tid = threadIdx.x;
    const int tx = tid & 15;
    const int ty = tid >> 4;
    const int bm = blockIdx.y * GBM;
    const int bn = blockIdx.x * GBN;

    unsigned long long acc[4][4];
    #pragma unroll
    for (int p = 0; p < 4; p++)
        #pragma unroll
        for (int j = 0; j < 4; j++) acc[p][j] = 0ull;

    const int lr = tid >> 2;
    const int lc = (tid & 3) * 4;

    for (int k0 = 0; k0 < K; k0 += GBK) {
        #pragma unroll
        for (int r = 0; r < 2; r++) {
            int mrow = bm + lr + r * 64;
            float4 v = make_float4(0.f, 0.f, 0.f, 0.f);
            if (mrow < M && (k0 + lc) < K)
                v = *reinterpret_cast<const float4*>(A + (size_t)mrow * lda + k0 + lc);
            if (RELU_A) {
                v.x = fmaxf(v.x, 0.f); v.y = fmaxf(v.y, 0.f);
                v.z = fmaxf(v.z, 0.f); v.w = fmaxf(v.w, 0.f);
            }
            As[lc + 0][lr + r * 64] = v.x; As[lc + 1][lr + r * 64] = v.y;
            As[lc + 2][lr + r * 64] = v.z; As[lc + 3][lr + r * 64] = v.w;
        }
        {
            int nrow = bn + lr;
            float4 v = make_float4(0.f, 0.f, 0.f, 0.f);
            if (nrow < N && (k0 + lc) < K)
                v = *reinterpret_cast<const float4*>(B + (size_t)nrow * ldb + k0 + lc);
            Bs[lc + 0][lr] = v.x; Bs[lc + 1][lr] = v.y;
            Bs[lc + 2][lr] = v.z; Bs[lc + 3][lr] = v.w;
        }
        __syncthreads();
        #pragma unroll
        for (int kk = 0; kk < GBK; kk++) {
            const unsigned long long* ap =
                reinterpret_cast<const unsigned long long*>(&As[kk][ty * 8]);
            unsigned long long a0 = ap[0], a1 = ap[1], a2 = ap[2], a3 = ap[3];
            const float4 bq = *reinterpret_cast<const float4*>(&Bs[kk][tx * 4]);
            unsigned long long b0 = pack2(bq.x, bq.x), b1 = pack2(bq.y, bq.y);
            unsigned long long b2 = pack2(bq.z, bq.z), b3 = pack2(bq.w, bq.w);
            fma2(acc[0][0], a0, b0); fma2(acc[0][1], a0, b1); fma2(acc[0][2], a0, b2); fma2(acc[0][3], a0, b3);
            fma2(acc[1][0], a1, b0); fma2(acc[1][1], a1, b1); fma2(acc[1][2], a1, b2); fma2(acc[1][3], a1, b3);
            fma2(acc[2][0], a2, b0); fma2(acc[2][1], a2, b1); fma2(acc[2][2], a2, b2); fma2(acc[2][3], a2, b3);
            fma2(acc[3][0], a3, b0); fma2(acc[3][1], a3, b1); fma2(acc[3][2], a3, b2); fma2(acc[3][3], a3, b3);
        }
        __syncthreads();
    }

    #pragma unroll
    for (int j = 0; j < 4; j++) {
        int n = bn + tx * 4 + j;
        if (n >= N) continue;
        float bv = bias[n];
        #pragma unroll
        for (int p = 0; p < 4; p++) {
            float2 cc = unpack2(acc[p][j]);
            int m0 = bm + ty * 8 + 2 * p;
            float lo = cc.x + bv, hi = cc.y + bv;
            if (RELU_C) { lo = fmaxf(lo, 0.f); hi = fmaxf(hi, 0.f); }
            if (m0 < M) {
                C[(size_t)m0 * ldc + n] = lo;
                if (C2) C2[(size_t)m0 * ldc2 + n] = lo;
            }
            if (m0 + 1 < M) {
                C[(size_t)(m0 + 1) * ldc + n] = hi;
                if (C2) C2[(size_t)(m0 + 1) * ldc2 + n] = hi;
            }
        }
    }
}

// ---------------- K3: attention per (b, head) -> query-mean of ctx ----------------
#define SSTR 448
#define ATT_SMEM ((3*LH*SSTR + LH*LH + LH + 4) * 4)

__global__ __launch_bounds__(256) void attn_mean_kernel(
    const __half* __restrict__ qkv, const int* __restrict__ hist_nids,
    float* __restrict__ ctx_mean)
{
    extern __shared__ float sm[];
    float* sq = sm;
    float* sk = sq + LH * SSTR;
    float* sv = sk + LH * SSTR;
    float* sc = sv + LH * SSTR;
    float* wb = sc + LH * LH;

    int b = blockIdx.x;
    int h = blockIdx.y;
    int tid = threadIdx.x;
    const float scale = (float)(1.0 / sqrt(430.0));

    size_t base = (size_t)b * LH * QKVN + (size_t)h * DHEAD;
    for (int idx = tid; idx < LH * (SSTR / 2); idx += 256) {
        int l = idx / (SSTR / 2), dp = idx - l * (SSTR / 2);
        int dd = dp * 2;
        float qx = 0.f, qy = 0.f, kx = 0.f, ky = 0.f, vx = 0.f, vy = 0.f;
        if (dd < DHEAD) {
            size_t o = base + (size_t)l * QKVN + dd;
            float2 qq = __half22float2(*(const __half2*)(qkv + o));
            float2 kk = __half22float2(*(const __half2*)(qkv + o + DIM));
            float2 vv = __half22float2(*(const __half2*)(qkv + o + 2 * DIM));
            qx = qq.x; qy = qq.y; kx = kk.x; ky = kk.y; vx = vv.x; vy = vv.y;
        }
        sq[l * SSTR + dd] = qx; sq[l * SSTR + dd + 1] = qy;
        sk[l * SSTR + dd] = kx; sk[l * SSTR + dd + 1] = ky;
        sv[l * SSTR + dd] = vx; sv[l * SSTR + dd + 1] = vy;
    }
    __syncthreads();

    int w = tid >> 5, lane = tid & 31;
    for (int qi = w; qi < LH; qi += 8) {
        float qreg[14];
        #pragma unroll
        for (int t = 0; t < 14; t++) qreg[t] = sq[qi * SSTR + lane + 32 * t];
        for (int ki = 0; ki < LH; ki++) {
            float s = 0.f;
            #pragma unroll
            for (int t = 0; t < 14; t++) s += qreg[t] * sk[ki * SSTR + lane + 32 * t];
            #pragma unroll
            for (int off = 16; off > 0; off >>= 1) s += __shfl_xor_sync(0xffffffffu, s, off);
            if (lane == 0) {
                int hn = hist_nids[b * LH + ki];
                bool masked = (hn == 0) && (ki != LH - 1);
                sc[qi * LH + ki] = masked ? -1e30f : s * scale;
            }
        }
    }
    __syncthreads();

    if (tid < LH) {
        int qi = tid;
        float mx = -1e30f;
        for (int ki = 0; ki < LH; ki++) mx = fmaxf(mx, sc[qi * LH + ki]);
        float sum = 0.f;
        for (int ki = 0; ki < LH; ki++) {
            float e = expf(sc[qi * LH + ki] - mx);
            sc[qi * LH + ki] = e;
            sum += e;
        }
        float inv = 1.f / sum;
        for (int ki = 0; ki < LH; ki++) sc[qi * LH + ki] *= inv;
    }
    __syncthreads();

    if (tid < LH) {
        int ki = tid;
        float s = 0.f;
        for (int qi = 0; qi < LH; qi++) s += sc[qi * LH + ki];
        wb[ki] = s * (1.0f / LH);
    }
    __syncthreads();

    for (int dd = tid; dd < DHEAD; dd += 256) {
        float s = 0.f;
        #pragma unroll
        for (int ki = 0; ki < LH; ki++) s += wb[ki] * sv[ki * SSTR + dd];
        ctx_mean[(size_t)b * DIM + (size_t)h * DHEAD + dd] = s;
    }
}

// ---------------- host ----------------
extern "C" void kernel_launch(void* const* d_in, const int* in_sizes, int n_in,
                              void* d_out, int out_size)
{
    const int*   nids       = (const int*)  d_in[0];
    const int*   hist_nids  = (const int*)  d_in[1];
    const int*   anon_ids   = (const int*)  d_in[2];
    const int*   hist_eids  = (const int*)  d_in[3];
    const float* hist_ts    = (const float*)d_in[4];
    const int*   hist_dirs  = (const int*)  d_in[5];
    const float* node_emb   = (const float*)d_in[6];
    const float* edge_emb   = (const float*)d_in[7];
    const float* anony_emb  = (const float*)d_in[8];
    const float* time_w     = (const float*)d_in[9];
    const float* time_b     = (const float*)d_in[10];
    const float* in_proj_w  = (const float*)d_in[11];
    const float* in_proj_b  = (const float*)d_in[12];
    const float* out_proj_w = (const float*)d_in[13];
    const float* out_proj_b = (const float*)d_in[14];
    const float* outfn_w    = (const float*)d_in[15];
    const float* outfn_b    = (const float*)d_in[16];
    const float* fc1_w      = (const float*)d_in[17];
    const float* fc1_b      = (const float*)d_in[18];
    const float* fc2_w      = (const float*)d_in[19];
    const float* fc2_b      = (const float*)d_in[20];

    float* out     = (float*)d_out;
    float* out_hl  = out;
    float* out_hr  = out + (size_t)BSZ * NFEAT;
    float* out_pts = out + (size_t)2 * BSZ * NFEAT;

    __half *a16, *b16, *qkv;
    float *aq, *cm, *mbuf, *xbuf, *hbuf;
    cudaGetSymbolAddress((void**)&a16, g_a);
    cudaGetSymbolAddress((void**)&b16, g_b);
    cudaGetSymbolAddress((void**)&aq,  g_aq);
    cudaGetSymbolAddress((void**)&qkv, g_qkv);
    cudaGetSymbolAddress((void**)&cm,  g_cm);
    cudaGetSymbolAddress((void**)&mbuf, g_m);
    cudaGetSymbolAddress((void**)&xbuf, g_x);
    cudaGetSymbolAddress((void**)&hbuf, g_h);

    cudaFuncSetAttribute(attn_mean_kernel,
                         cudaFuncAttributeMaxDynamicSharedMemorySize, ATT_SMEM);
    cudaFuncSetAttribute(qkv_mma_kernel,
                         cudaFuncAttributeMaxDynamicSharedMemorySize, QSM_TOTAL);

    // K1 family: build operands
    build_full_kernel<<<NROWS, 128>>>(nids, hist_nids, anon_ids, hist_eids, hist_ts,
                                      hist_dirs, node_emb, edge_emb, anony_emb,
                                      time_w, time_b, out_pts);
    {
        size_t tot = (size_t)NPAD2 * KP2;
        split_b_kernel<<<(int)((tot + 255) / 256), 256>>>(in_proj_w);
    }
    anony_proj_kernel<<<dim3((QKVN + 255) / 256, LH + 1), 256>>>(anony_emb, in_proj_w);

    // K2: qkv GEMM, single-term fp16 mma.sync (R5 geometry, fp16 out)
    {
        dim3 grid(NPAD2 / 128, NROWS / 128);
        qkv_mma_kernel<<<grid, 256, QSM_TOTAL>>>(a16, b16, in_proj_b, aq, anon_ids, qkv);
    }

    // K3: attention -> ctx mean over L
    attn_mean_kernel<<<dim3(BSZ, NHEAD), 256, ATT_SMEM>>>(qkv, hist_nids, cm);

    // K4: m = ctx_mean @ out_proj_w^T + b
    {
        dim3 grid((DIM + GBN - 1) / GBN, BSZ / GBM);
        gemm_nt<false, false><<<grid, 256>>>(cm, DIM, out_proj_w, DIM, out_proj_b,
                                             mbuf, DIM, (float*)nullptr, 0,
                                             BSZ, DIM, DIM);
    }
    // K5: hl = relu(m) @ outfn_w^T + b -> d_out AND x[:, :172]
    {
        dim3 grid((NFEAT + GBN - 1) / GBN, BSZ / GBM);
        gemm_nt<true, false><<<grid, 256>>>(mbuf, DIM, outfn_w, DIM, outfn_b,
                                            out_hl, NFEAT, xbuf, DIM,
                                            BSZ, NFEAT, DIM);
    }
    // K6: h = relu(x @ fc1_w^T + b)
    {
        dim3 grid((NFEAT + GBN - 1) / GBN, BSZ / GBM);
        gemm_nt<false, true><<<grid, 256>>>(xbuf, DIM, fc1_w, DIM, fc1_b,
                                            hbuf, NFEAT, (float*)nullptr, 0,
                                            BSZ, NFEAT, DIM);
    }
    // K7: hr = h @ fc2_w^T + b -> d_out
    {
        dim3 grid((NFEAT + GBN - 1) / GBN, BSZ / GBM);
        gemm_nt<false, false><<<grid, 256>>>(hbuf, NFEAT, fc2_w, NFEAT, fc2_b,
                                             out_hr, NFEAT, (float*)nullptr, 0,
                                             BSZ, NFEAT, NFEAT);
    }
}

// round 9
// speedup vs baseline: 1.6403x; 1.4287x over previous
#include <cuda_runtime.h>
#include <cuda_bf16.h>
#include <cuda_fp16.h>
#include <math.h>
#include <stdint.h>

// ---------------- problem constants ----------------
#define BSZ   8192
#define LH    20
#define NFEAT 172
#define DIM   860
#define DHEAD 430
#define NHEAD 2
#define QKVN  2580
#define NROWS (BSZ*LH)      // 163840
#define KP2   704           // reduced K (no anony block): 11*64
#define NC    (KP2/64)
#define NPAD2 2688          // 21*128
#define KP3   896           // DIM padded: 14*64
#define NC3   (KP3/64)

// ---------------- scratch ----------------
__device__ __half g_a[(size_t)NROWS * KP2];        // fp16 activations
__device__ __half g_b[(size_t)NPAD2 * KP2];        // fp16 qkv weights
__device__ float  g_aq[(size_t)(LH + 1) * QKVN];   // anony projection (fp32)
__device__ __half g_qkv[(size_t)NROWS * QKVN];     // fp16 qkv
__device__ __half g_cm16[(size_t)BSZ * KP3];       // ctx mean (fp16, K-padded)
__device__ __half g_relum[(size_t)BSZ * KP3];      // relu(out_proj(cm)) fp16
__device__ __half g_x16[(size_t)BSZ * KP3];        // [hl | lef] fp16
__device__ float  g_h[(size_t)BSZ * NFEAT];        // fc1 output fp32
__device__ __half g_wo16[(size_t)896 * KP3];       // out_proj_w fp16 padded
__device__ __half g_wf16[(size_t)256 * KP3];       // outfn_w fp16 padded
__device__ __half g_wfc1[(size_t)256 * KP3];       // fc1_w fp16 padded

// ---------------- helpers ----------------
__device__ __forceinline__ uint32_t smem_u32(const void* p) {
    uint32_t a;
    asm("{ .reg .u64 t; cvta.to.shared.u64 t, %1; cvt.u32.u64 %0, t; }" : "=r"(a) : "l"(p));
    return a;
}
__device__ __forceinline__ void cpa16(uint32_t s, const void* g) {
    asm volatile("cp.async.cg.shared.global [%0], [%1], 16;" :: "r"(s), "l"(g));
}
#define CP_COMMIT() asm volatile("cp.async.commit_group;" ::: "memory")
#define CP_WAIT1()  asm volatile("cp.async.wait_group 1;" ::: "memory")

#define LDSM4(r, addr) \
    asm volatile("ldmatrix.sync.aligned.m8n8.x4.shared.b16 {%0,%1,%2,%3}, [%4];" \
        : "=r"((r)[0]), "=r"((r)[1]), "=r"((r)[2]), "=r"((r)[3]) : "r"(addr) : "memory")
#define MMA_F16(acc, a, b0, b1) \
    asm volatile("mma.sync.aligned.m16n8k16.row.col.f32.f16.f16.f32 " \
        "{%0,%1,%2,%3}, {%4,%5,%6,%7}, {%8,%9}, {%0,%1,%2,%3};" \
        : "+f"((acc)[0]), "+f"((acc)[1]), "+f"((acc)[2]), "+f"((acc)[3]) \
        : "r"((a)[0]), "r"((a)[1]), "r"((a)[2]), "r"((a)[3]), "r"(b0), "r"(b1))

// fp32 Cody-Waite cos: exact for |x| <= ~1e5 (k < 2^16), abs err ~4e-6.
__device__ __forceinline__ float cos_cw(float x) {
    const float c1 = 6.28125f;                                          // 8-bit mantissa
    const float c2 = (float)(6.283185307179586476925286766559 - 6.28125);
    const float c3 = (float)(6.283185307179586476925286766559 - 6.28125
                             - (double)((float)(6.283185307179586476925286766559 - 6.28125)));
    float k = rintf(x * 0.15915494309189535f);
    float r = fmaf(k, -c1, x);
    r = fmaf(k, -c2, r);
    r = fmaf(k, -c3, r);
    return cosf(r);
}
__device__ __forceinline__ unsigned long long pack2(float lo, float hi) {
    unsigned long long r;
    asm("mov.b64 %0, {%1, %2};" : "=l"(r) : "f"(lo), "f"(hi));
    return r;
}
__device__ __forceinline__ void fma2(unsigned long long& d, unsigned long long a, unsigned long long b) {
    asm("fma.rn.f32x2 %0, %1, %2, %3;" : "=l"(d) : "l"(a), "l"(b), "l"(d));
}
__device__ __forceinline__ float2 unpack2(unsigned long long v) {
    float2 f;
    asm("mov.b64 {%0, %1}, %2;" : "=f"(f.x), "=f"(f.y) : "l"(v));
    return f;
}

// ---------------- K1: gather + time-encode -> fp16 A; lef -> x16 ----------------
__global__ void build_full_kernel(
    const int* __restrict__ nids, const int* __restrict__ hist_nids,
    const int* __restrict__ anon_ids, const int* __restrict__ hist_eids,
    const float* __restrict__ hist_ts, const int* __restrict__ hist_dirs,
    const float* __restrict__ node_emb, const float* __restrict__ edge_emb,
    const float* __restrict__ anony_emb, const float* __restrict__ time_w,
    const float* __restrict__ time_b, float* __restrict__ out_prevts)
{
    int row = blockIdx.x;
    int b = row / LH;
    int l = row - b * LH;
    int nid = nids[b];
    int hn  = hist_nids[row];
    int d   = hist_dirs[row];
    int src = d ? nid : hn;
    int dst = d ? hn  : nid;
    int aid = anon_ids[row];
    int eid = hist_eids[row];
    float tlast = hist_ts[b * LH + (LH - 1)];
    float dt = __fsub_rn(tlast, hist_ts[row]);
    bool last = (l == LH - 1);

    for (int j = threadIdx.x; j < KP2; j += blockDim.x) {
        float val = 0.0f;
        if (j < 172)      val = node_emb[(size_t)src * NFEAT + j];
        else if (j < 344) val = node_emb[(size_t)dst * NFEAT + (j - 172)];
        else if (j < 516) val = edge_emb[(size_t)eid * NFEAT + (j - 344)];
        else if (j < 688) {
            int jj = j - 516;
            float x = __fmul_rn(dt, time_w[jj]);
            x = __fadd_rn(x, time_b[jj]);
            val = cos_cw(x);
        }
        if (last && j < 516) {
            int xo = (j < 344) ? (NFEAT + j) : (NFEAT + j + NFEAT);  // edge shifts past anony
            g_x16[(size_t)b * KP3 + xo] = __float2half_rn(val);
            val = 0.0f;
        }
        g_a[(size_t)row * KP2 + j] = __float2half_rn(val);
    }
    if (last) {
        for (int j = threadIdx.x; j < NFEAT; j += blockDim.x)
            g_x16[(size_t)b * KP3 + NFEAT + 344 + j] =
                __float2half_rn(anony_emb[(size_t)aid * NFEAT + j]);
        if (threadIdx.x == 0) out_prevts[b] = tlast;
    }
}

// ---------------- K1b: in_proj_w (minus anony cols) -> padded fp16 ----------------
__global__ void split_b_kernel(const float* __restrict__ W)
{
    size_t idx = (size_t)blockIdx.x * blockDim.x + threadIdx.x;
    if (idx >= (size_t)NPAD2 * KP2) return;
    int r = (int)(idx / KP2);
    int k = (int)(idx - (size_t)r * KP2);
    float v = 0.0f;
    if (r < QKVN) {
        if (k < 344)      v = W[(size_t)r * DIM + k];
        else if (k < 688) v = W[(size_t)r * DIM + k + NFEAT];
    }
    g_b[idx] = __float2half_rn(v);
}

// ---------------- K1c: AQ = anony_emb @ W[:,344:516]^T ----------------
__global__ void anony_proj_kernel(const float* __restrict__ anony_emb,
                                  const float* __restrict__ W)
{
    int n = blockIdx.x * blockDim.x + threadIdx.x;
    int a = blockIdx.y;
    if (n >= QKVN) return;
    float s = 0.0f;
    const float* wr = W + (size_t)n * DIM + 344;
    const float* ar = anony_emb + (size_t)a * NFEAT;
    #pragma unroll 4
    for (int k = 0; k < NFEAT; k++) s += ar[k] * wr[k];
    g_aq[(size_t)a * QKVN + n] = s;
}

// ---------------- K1d: generic weight -> padded fp16 converter ----------------
// W is [nreal x 860] row-major; dst is [npad x KP3].
__global__ void conv_w_kernel(const float* __restrict__ W, __half* __restrict__ dst,
                              int nreal, int npad)
{
    size_t idx = (size_t)blockIdx.x * blockDim.x + threadIdx.x;
    if (idx >= (size_t)npad * KP3) return;
    int r = (int)(idx / KP3);
    int k = (int)(idx - (size_t)r * KP3);
    float v = (r < nreal && k < DIM) ? W[(size_t)r * DIM + k] : 0.0f;
    dst[idx] = __float2half_rn(v);
}

// ---------------- K2: qkv GEMM (R7 config, frozen) ----------------
#define QSM_STAGE 32768
#define QSM_TOTAL (3*QSM_STAGE)

__device__ __forceinline__ void qkv_load_stage(
    uint32_t sb, int stage, int c, int bm, int bn, int tid,
    const __half* A, const __half* B)
{
    uint32_t sbase = sb + stage * QSM_STAGE;
    const size_t kof = (size_t)c * 64;
    #pragma unroll
    for (int it = 0; it < 4; it++) {
        int cid = tid + it * 256;
        int r  = cid >> 3;
        int kc = cid & 7;
        uint32_t soff = (uint32_t)(r * 128 + ((kc ^ (r & 7)) << 4));
        const char* ga = (const char*)(A + (size_t)(bm + r) * KP2 + kof) + kc * 16;
        const char* gb = (const char*)(B + (size_t)(bn + r) * KP2 + kof) + kc * 16;
        cpa16(sbase +         soff, ga);
        cpa16(sbase + 16384 + soff, gb);
    }
    CP_COMMIT();
}

__global__ __launch_bounds__(256, 2) void qkv_mma_kernel(
    const __half* __restrict__ A, const __half* __restrict__ B,
    const float* __restrict__ bias, const float* __restrict__ AQ,
    const int* __restrict__ anon_ids, __half* __restrict__ C)
{
    extern __shared__ char smem[];
    const uint32_t sb = smem_u32(smem);
    const int tid = threadIdx.x;
    const int wid = tid >> 5;
    const int lane = tid & 31;
    const int warp_m = wid >> 2;
    const int warp_n = wid & 3;
    const int bm = blockIdx.y * 128;
    const int bn = blockIdx.x * 128;

    float acc[4][4][4];
    #pragma unroll
    for (int mi = 0; mi < 4; mi++)
        #pragma unroll
        for (int nf = 0; nf < 4; nf++)
            #pragma unroll
            for (int t = 0; t < 4; t++) acc[mi][nf][t] = 0.0f;

    qkv_load_stage(sb, 0, 0, bm, bn, tid, A, B);
    qkv_load_stage(sb, 1, 1, bm, bn, tid, A, B);

    for (int c = 0; c < NC; c++) {
        const int stage = c % 3;
        CP_WAIT1();
        __syncthreads();
        if (c + 2 < NC)
            qkv_load_stage(sb, (c + 2) % 3, c + 2, bm, bn, tid, A, B);

        const uint32_t sA = sb + stage * QSM_STAGE;
        const uint32_t sB = sA + 16384;
        #pragma unroll
        for (int kk = 0; kk < 4; kk++) {
            uint32_t ah[4][4];
            #pragma unroll
            for (int mi = 0; mi < 4; mi++) {
                int mrow = warp_m * 64 + mi * 16 + (lane & 15);
                int chunk = kk * 2 + (lane >> 4);
                uint32_t addr = sA + mrow * 128 + ((chunk ^ (mrow & 7)) << 4);
                LDSM4(ah[mi], addr);
            }
            uint32_t bh[2][4];
            #pragma unroll
            for (int np = 0; np < 2; np++) {
                int nrow = warp_n * 32 + np * 16 + ((lane >> 4) << 3) + (lane & 7);
                int chunk = kk * 2 + ((lane >> 3) & 1);
                uint32_t addr = sB + nrow * 128 + ((chunk ^ (nrow & 7)) << 4);
                LDSM4(bh[np], addr);
            }
            #pragma unroll
            for (int mi = 0; mi < 4; mi++) {
                #pragma unroll
                for (int nf = 0; nf < 4; nf++) {
                    int np = nf >> 1, ri = (nf & 1) * 2;
                    MMA_F16(acc[mi][nf], ah[mi], bh[np][ri], bh[np][ri + 1]);
                }
            }
        }
    }

    const int group = lane >> 2;
    const int tc2 = (lane & 3) * 2;
    #pragma unroll
    for (int mi = 0; mi < 4; mi++) {
        int r0 = bm + warp_m * 64 + mi * 16 + group;
        int r1 = r0 + 8;
        int aid0 = anon_ids[r0];
        int aid1 = anon_ids[r1];
        bool nl0 = (r0 % LH) != (LH - 1);
        bool nl1 = (r1 % LH) != (LH - 1);
        #pragma unroll
        for (int nf = 0; nf < 4; nf++) {
            int n = bn + warp_n * 32 + nf * 8 + tc2;
            if (n >= QKVN) continue;
            float2 bv = *(const float2*)(bias + n);
            float2 o0, o1;
            o0.x = acc[mi][nf][0] + bv.x;
            o0.y = acc[mi][nf][1] + bv.y;
            o1.x = acc[mi][nf][2] + bv.x;
            o1.y = acc[mi][nf][3] + bv.y;
            if (nl0) {
                float2 q = *(const float2*)(AQ + (size_t)aid0 * QKVN + n);
                o0.x += q.x; o0.y += q.y;
            }
            if (nl1) {
                float2 q = *(const float2*)(AQ + (size_t)aid1 * QKVN + n);
                o1.x += q.x; o1.y += q.y;
            }
            *(__half2*)(C + (size_t)r0 * QKVN + n) = __floats2half2_rn(o0.x, o0.y);
            *(__half2*)(C + (size_t)r1 * QKVN + n) = __floats2half2_rn(o1.x, o1.y);
        }
    }
}

// ---------------- tail fp16 MMA kernel (K4/K5/K6) ----------------
__device__ __forceinline__ void tail_load_stage(
    uint32_t sb, int stage, int c, int bm, int bn, int tid,
    const __half* A, int akpad, const __half* B, int bkpad)
{
    uint32_t sbase = sb + stage * QSM_STAGE;
    const size_t kof = (size_t)c * 64;
    #pragma unroll
    for (int it = 0; it < 4; it++) {
        int cid = tid + it * 256;
        int r  = cid >> 3;
        int kc = cid & 7;
        uint32_t soff = (uint32_t)(r * 128 + ((kc ^ (r & 7)) << 4));
        const char* ga = (const char*)(A + (size_t)(bm + r) * akpad + kof) + kc * 16;
        const char* gb = (const char*)(B + (size_t)(bn + r) * bkpad + kof) + kc * 16;
        cpa16(sbase +         soff, ga);
        cpa16(sbase + 16384 + soff, gb);
    }
    CP_COMMIT();
}

template<bool RELU, bool F32OUT, bool F16OUT>
__global__ __launch_bounds__(256, 2) void tail_mma_kernel(
    const __half* __restrict__ A, int akpad,
    const __half* __restrict__ B, int bkpad, int nchunks,
    const float* __restrict__ bias, int nreal,
    float* __restrict__ C32, int ldc32,
    __half* __restrict__ C16, int ldc16)
{
    extern __shared__ char smem[];
    const uint32_t sb = smem_u32(smem);
    const int tid = threadIdx.x;
    const int wid = tid >> 5;
    const int lane = tid & 31;
    const int warp_m = wid >> 2;
    const int warp_n = wid & 3;
    const int bm = blockIdx.y * 128;
    const int bn = blockIdx.x * 128;

    float acc[4][4][4];
    #pragma unroll
    for (int mi = 0; mi < 4; mi++)
        #pragma unroll
        for (int nf = 0; nf < 4; nf++)
            #pragma unroll
            for (int t = 0; t < 4; t++) acc[mi][nf][t] = 0.0f;

    tail_load_stage(sb, 0, 0, bm, bn, tid, A, akpad, B, bkpad);
    tail_load_stage(sb, 1, 1, bm, bn, tid, A, akpad, B, bkpad);

    for (int c = 0; c < nchunks; c++) {
        const int stage = c % 3;
        CP_WAIT1();
        __syncthreads();
        if (c + 2 < nchunks)
            tail_load_stage(sb, (c + 2) % 3, c + 2, bm, bn, tid, A, akpad, B, bkpad);

        const uint32_t sA = sb + stage * QSM_STAGE;
        const uint32_t sB = sA + 16384;
        #pragma unroll
        for (int kk = 0; kk < 4; kk++) {
            uint32_t ah[4][4];
            #pragma unroll
            for (int mi = 0; mi < 4; mi++) {
                int mrow = warp_m * 64 + mi * 16 + (lane & 15);
                int chunk = kk * 2 + (lane >> 4);
                uint32_t addr = sA + mrow * 128 + ((chunk ^ (mrow & 7)) << 4);
                LDSM4(ah[mi], addr);
            }
            uint32_t bh[2][4];
            #pragma unroll
            for (int np = 0; np < 2; np++) {
                int nrow = warp_n * 32 + np * 16 + ((lane >> 4) << 3) + (lane & 7);
                int chunk = kk * 2 + ((lane >> 3) & 1);
                uint32_t addr = sB + nrow * 128 + ((chunk ^ (nrow & 7)) << 4);
                LDSM4(bh[np], addr);
            }
            #pragma unroll
            for (int mi = 0; mi < 4; mi++) {
                #pragma unroll
                for (int nf = 0; nf < 4; nf++) {
                    int np = nf >> 1, ri = (nf & 1) * 2;
                    MMA_F16(acc[mi][nf], ah[mi], bh[np][ri], bh[np][ri + 1]);
                }
            }
        }
    }

    const int group = lane >> 2;
    const int tc2 = (lane & 3) * 2;
    #pragma unroll
    for (int mi = 0; mi < 4; mi++) {
        int r0 = bm + warp_m * 64 + mi * 16 + group;
        int r1 = r0 + 8;
        #pragma unroll
        for (int nf = 0; nf < 4; nf++) {
            int n = bn + warp_n * 32 + nf * 8 + tc2;
            if (n >= nreal) continue;
            float2 bv = *(const float2*)(bias + n);
            float2 o0, o1;
            o0.x = acc[mi][nf][0] + bv.x;
            o0.y = acc[mi][nf][1] + bv.y;
            o1.x = acc[mi][nf][2] + bv.x;
            o1.y = acc[mi][nf][3] + bv.y;
            if (RELU) {
                o0.x = fmaxf(o0.x, 0.f); o0.y = fmaxf(o0.y, 0.f);
                o1.x = fmaxf(o1.x, 0.f); o1.y = fmaxf(o1.y, 0.f);
            }
            if (F32OUT) {
                *(float2*)(C32 + (size_t)r0 * ldc32 + n) = o0;
                *(float2*)(C32 + (size_t)r1 * ldc32 + n) = o1;
            }
            if (F16OUT) {
                *(__half2*)(C16 + (size_t)r0 * ldc16 + n) = __floats2half2_rn(o0.x, o0.y);
                *(__half2*)(C16 + (size_t)r1 * ldc16 + n) = __floats2half2_rn(o1.x, o1.y);
            }
        }
    }
}

// ---------------- SIMT f32x2 GEMM (K7 only) ----------------
#define GBM 128
#define GBN 64
#define GBK 16

__global__ __launch_bounds__(256) void gemm_nt(
    const float* __restrict__ A, int lda,
    const float* __restrict__ B, int ldb,
    const float* __restrict__ bias,
    float* __restrict__ C, int ldc,
    int M, int N, int K)
{
    __shared__ float As[GBK][GBM + 4];
    __shared__ float Bs[GBK][GBN + 4];
    const int tid = threadIdx.x;
    const int tx = tid & 15;
    const int ty = tid >> 4;
    const int bm = blockIdx.y * GBM;
    const int bn = blockIdx.x * GBN;

    unsigned long long acc[4][4];
    #pragma unroll
    for (int p = 0; p < 4; p++)
        #pragma unroll
        for (int j = 0; j < 4; j++) acc[p][j] = 0ull;

    const int lr = tid >> 2;
    const int lc = (tid & 3) * 4;

    for (int k0 = 0; k0 < K; k0 += GBK) {
        #pragma unroll
        for (int r = 0; r < 2; r++) {
            int mrow = bm + lr + r * 64;
            float4 v = make_float4(0.f, 0.f, 0.f, 0.f);
            if (mrow < M && (k0 + lc) < K)
                v = *reinterpret_cast<const float4*>(A + (size_t)mrow * lda + k0 + lc);
            As[lc + 0][lr + r * 64] = v.x; As[lc + 1][lr + r * 64] = v.y;
            As[lc + 2][lr + r * 64] = v.z; As[lc + 3][lr + r * 64] = v.w;
        }
        {
            int nrow = bn + lr;
            float4 v = make_float4(0.f, 0.f, 0.f, 0.f);
            if (nrow < N && (k0 + lc) < K)
                v = *reinterpret_cast<const float4*>(B + (size_t)nrow * ldb + k0 + lc);
            Bs[lc + 0][lr] = v.x; Bs[lc + 1][lr] = v.y;
            Bs[lc + 2][lr] = v.z; Bs[lc + 3][lr] = v.w;
        }
        __syncthreads();
        #pragma unroll
        for (int kk = 0; kk < GBK; kk++) {
            const unsigned long long* ap =
                reinterpret_cast<const unsigned long long*>(&As[kk][ty * 8]);
            unsigned long long a0 = ap[0], a1 = ap[1], a2 = ap[2], a3 = ap[3];
            const float4 bq = *reinterpret_cast<const float4*>(&Bs[kk][tx * 4]);
            unsigned long long b0 = pack2(bq.x, bq.x), b1 = pack2(bq.y, bq.y);
            unsigned long long b2 = pack2(bq.z, bq.z), b3 = pack2(bq.w, bq.w);
            fma2(acc[0][0], a0, b0); fma2(acc[0][1], a0, b1); fma2(acc[0][2], a0, b2); fma2(acc[0][3], a0, b3);
            fma2(acc[1][0], a1, b0); fma2(acc[1][1], a1, b1); fma2(acc[1][2], a1, b2); fma2(acc[1][3], a1, b3);
            fma2(acc[2][0], a2, b0); fma2(acc[2][1], a2, b1); fma2(acc[2][2], a2, b2); fma2(acc[2][3], a2, b3);
            fma2(acc[3][0], a3, b0); fma2(acc[3][1], a3, b1); fma2(acc[3][2], a3, b2); fma2(acc[3][3], a3, b3);
        }
        __syncthreads();
    }

    #pragma unroll
    for (int j = 0; j < 4; j++) {
        int n = bn + tx * 4 + j;
        if (n >= N) continue;
        float bv = bias[n];
        #pragma unroll
        for (int p = 0; p < 4; p++) {
            float2 cc = unpack2(acc[p][j]);
            int m0 = bm + ty * 8 + 2 * p;
            if (m0 < M)     C[(size_t)m0 * ldc + n] = cc.x + bv;
            if (m0 + 1 < M) C[(size_t)(m0 + 1) * ldc + n] = cc.y + bv;
        }
    }
}

// ---------------- K3: attention -> query-mean of ctx (half2 smem) ----------------
#define AT2 224   // half2 per row (430 -> 215 used, padded)
#define ATT_SMEM2 ((3*LH*AT2)*4 + (LH*LH + LH + 8)*4)

__global__ __launch_bounds__(256) void attn_mean_kernel(
    const __half* __restrict__ qkv, const int* __restrict__ hist_nids,
    __half* __restrict__ cm16)
{
    extern __shared__ char smraw[];
    __half2* sq = (__half2*)smraw;
    __half2* sk = sq + LH * AT2;
    __half2* sv = sk + LH * AT2;
    float* sc = (float*)(sv + LH * AT2);
    float* wb = sc + LH * LH;

    int b = blockIdx.x;
    int h = blockIdx.y;
    int tid = threadIdx.x;
    const float scale = (float)(1.0 / sqrt(430.0));

    size_t base = (size_t)b * LH * QKVN + (size_t)h * DHEAD;
    __half2 hz = __floats2half2_rn(0.f, 0.f);
    for (int idx = tid; idx < LH * AT2; idx += 256) {
        int l = idx / AT2, dp = idx - l * AT2;
        __half2 q = hz, k = hz, v = hz;
        if (dp < DHEAD / 2) {
            size_t o = base + (size_t)l * QKVN + dp * 2;
            q = *(const __half2*)(qkv + o);
            k = *(const __half2*)(qkv + o + DIM);
            v = *(const __half2*)(qkv + o + 2 * DIM);
        }
        sq[idx] = q; sk[idx] = k; sv[idx] = v;
    }
    __syncthreads();

    int w = tid >> 5, lane = tid & 31;
    for (int qi = w; qi < LH; qi += 8) {
        __half2 qreg[7];
        #pragma unroll
        for (int t = 0; t < 7; t++) qreg[t] = sq[qi * AT2 + lane + 32 * t];
        for (int ki = 0; ki < LH; ki++) {
            float sx = 0.f, sy = 0.f;
            #pragma unroll
            for (int t = 0; t < 7; t++) {
                float2 qf = __half22float2(qreg[t]);
                float2 kf = __half22float2(sk[ki * AT2 + lane + 32 * t]);
                sx = fmaf(qf.x, kf.x, sx);
                sy = fmaf(qf.y, kf.y, sy);
            }
            float s = sx + sy;
            #pragma unroll
            for (int off = 16; off > 0; off >>= 1) s += __shfl_xor_sync(0xffffffffu, s, off);
            if (lane == 0) {
                int hn = hist_nids[b * LH + ki];
                bool masked = (hn == 0) && (ki != LH - 1);
                sc[qi * LH + ki] = masked ? -1e30f : s * scale;
            }
        }
    }
    __syncthreads();

    if (tid < LH) {
        int qi = tid;
        float mx = -1e30f;
        for (int ki = 0; ki < LH; ki++) mx = fmaxf(mx, sc[qi * LH + ki]);
        float sum = 0.f;
        for (int ki = 0; ki < LH; ki++) {
            float e = expf(sc[qi * LH + ki] - mx);
            sc[qi * LH + ki] = e;
            sum += e;
        }
        float inv = 1.f / sum;
        for (int ki = 0; ki < LH; ki++) sc[qi * LH + ki] *= inv;
    }
    __syncthreads();

    if (tid < LH) {
        int ki = tid;
        float s = 0.f;
        for (int qi = 0; qi < LH; qi++) s += sc[qi * LH + ki];
        wb[ki] = s * (1.0f / LH);
    }
    __syncthreads();

    for (int dp = tid; dp < DHEAD / 2; dp += 256) {
        float ax = 0.f, ay = 0.f;
        #pragma unroll
        for (int ki = 0; ki < LH; ki++) {
            float2 vf = __half22float2(sv[ki * AT2 + dp]);
            ax = fmaf(wb[ki], vf.x, ax);
            ay = fmaf(wb[ki], vf.y, ay);
        }
        *(__half2*)(cm16 + (size_t)b * KP3 + h * DHEAD + dp * 2) = __floats2half2_rn(ax, ay);
    }
}

// ---------------- host ----------------
extern "C" void kernel_launch(void* const* d_in, const int* in_sizes, int n_in,
                              void* d_out, int out_size)
{
    const int*   nids       = (const int*)  d_in[0];
    const int*   hist_nids  = (const int*)  d_in[1];
    const int*   anon_ids   = (const int*)  d_in[2];
    const int*   hist_eids  = (const int*)  d_in[3];
    const float* hist_ts    = (const float*)d_in[4];
    const int*   hist_dirs  = (const int*)  d_in[5];
    const float* node_emb   = (const float*)d_in[6];
    const float* edge_emb   = (const float*)d_in[7];
    const float* anony_emb  = (const float*)d_in[8];
    const float* time_w     = (const float*)d_in[9];
    const float* time_b     = (const float*)d_in[10];
    const float* in_proj_w  = (const float*)d_in[11];
    const float* in_proj_b  = (const float*)d_in[12];
    const float* out_proj_w = (const float*)d_in[13];
    const float* out_proj_b = (const float*)d_in[14];
    const float* outfn_w    = (const float*)d_in[15];
    const float* outfn_b    = (const float*)d_in[16];
    const float* fc1_w      = (const float*)d_in[17];
    const float* fc1_b      = (const float*)d_in[18];
    const float* fc2_w      = (const float*)d_in[19];
    const float* fc2_b      = (const float*)d_in[20];

    float* out     = (float*)d_out;
    float* out_hl  = out;
    float* out_hr  = out + (size_t)BSZ * NFEAT;
    float* out_pts = out + (size_t)2 * BSZ * NFEAT;

    __half *a16, *b16, *qkv, *cm16, *relum, *x16, *wo16, *wf16, *wfc1;
    float *aq, *hbuf;
    cudaGetSymbolAddress((void**)&a16,   g_a);
    cudaGetSymbolAddress((void**)&b16,   g_b);
    cudaGetSymbolAddress((void**)&aq,    g_aq);
    cudaGetSymbolAddress((void**)&qkv,   g_qkv);
    cudaGetSymbolAddress((void**)&cm16,  g_cm16);
    cudaGetSymbolAddress((void**)&relum, g_relum);
    cudaGetSymbolAddress((void**)&x16,   g_x16);
    cudaGetSymbolAddress((void**)&hbuf,  g_h);
    cudaGetSymbolAddress((void**)&wo16,  g_wo16);
    cudaGetSymbolAddress((void**)&wf16,  g_wf16);
    cudaGetSymbolAddress((void**)&wfc1,  g_wfc1);

    cudaFuncSetAttribute(attn_mean_kernel,
                         cudaFuncAttributeMaxDynamicSharedMemorySize, ATT_SMEM2);
    cudaFuncSetAttribute(qkv_mma_kernel,
                         cudaFuncAttributeMaxDynamicSharedMemorySize, QSM_TOTAL);
    cudaFuncSetAttribute(tail_mma_kernel<true, false, true>,
                         cudaFuncAttributeMaxDynamicSharedMemorySize, QSM_TOTAL);
    cudaFuncSetAttribute(tail_mma_kernel<false, true, true>,
                         cudaFuncAttributeMaxDynamicSharedMemorySize, QSM_TOTAL);
    cudaFuncSetAttribute(tail_mma_kernel<true, true, false>,
                         cudaFuncAttributeMaxDynamicSharedMemorySize, QSM_TOTAL);

    // K1 family
    build_full_kernel<<<NROWS, 128>>>(nids, hist_nids, anon_ids, hist_eids, hist_ts,
                                      hist_dirs, node_emb, edge_emb, anony_emb,
                                      time_w, time_b, out_pts);
    {
        size_t tot = (size_t)NPAD2 * KP2;
        split_b_kernel<<<(int)((tot + 255) / 256), 256>>>(in_proj_w);
    }
    anony_proj_kernel<<<dim3((QKVN + 255) / 256, LH + 1), 256>>>(anony_emb, in_proj_w);
    conv_w_kernel<<<(896 * KP3 + 255) / 256, 256>>>(out_proj_w, wo16, DIM, 896);
    conv_w_kernel<<<(256 * KP3 + 255) / 256, 256>>>(outfn_w, wf16, NFEAT, 256);
    conv_w_kernel<<<(256 * KP3 + 255) / 256, 256>>>(fc1_w, wfc1, NFEAT, 256);

    // K2: qkv GEMM
    {
        dim3 grid(NPAD2 / 128, NROWS / 128);
        qkv_mma_kernel<<<grid, 256, QSM_TOTAL>>>(a16, b16, in_proj_b, aq, anon_ids, qkv);
    }

    // K3: attention -> cm16
    attn_mean_kernel<<<dim3(BSZ, NHEAD), 256, ATT_SMEM2>>>(qkv, hist_nids, cm16);

    // K4: relum = relu(cm @ out_proj^T + b)   [fp16 MMA]
    tail_mma_kernel<true, false, true><<<dim3(896 / 128, BSZ / 128), 256, QSM_TOTAL>>>(
        cm16, KP3, wo16, KP3, NC3, out_proj_b, DIM,
        (float*)nullptr, 0, relum, KP3);

    // K5: hl = relum @ outfn^T + b -> out_hl (fp32) AND x16[:, :172] (fp16)
    tail_mma_kernel<false, true, true><<<dim3(256 / 128, BSZ / 128), 256, QSM_TOTAL>>>(
        relum, KP3, wf16, KP3, NC3, outfn_b, NFEAT,
        out_hl, NFEAT, x16, KP3);

    // K6: h = relu(x16 @ fc1^T + b) -> fp32
    tail_mma_kernel<true, true, false><<<dim3(256 / 128, BSZ / 128), 256, QSM_TOTAL>>>(
        x16, KP3, wfc1, KP3, NC3, fc1_b, NFEAT,
        hbuf, NFEAT, (__half*)nullptr, 0);

    // K7: hr = h @ fc2^T + b -> out_hr (fp32 SIMT)
    {
        dim3 grid((NFEAT + GBN - 1) / GBN, BSZ / GBM);
        gemm_nt<<<grid, 256>>>(hbuf, NFEAT, fc2_w, NFEAT, fc2_b,
                               out_hr, NFEAT, BSZ, NFEAT, NFEAT);
    }
}

// round 10
// speedup vs baseline: 1.9960x; 1.2169x over previous
#include <cuda_runtime.h>
#include <cuda_bf16.h>
#include <cuda_fp16.h>
#include <math.h>
#include <stdint.h>

// ---------------- problem constants ----------------
#define BSZ   8192
#define LH    20
#define NFEAT 172
#define DIM   860
#define DHEAD 430
#define NHEAD 2
#define QKVN  2580
#define NROWS (BSZ*LH)      // 163840
#define KP2   704           // reduced K (no anony block): 11*64
#define NC    (KP2/64)
#define QKN   1720          // q,k output cols
#define QKNP  1792          // padded: 14*128
#define KP3   896           // DIM padded: 14*64
#define NC3   (KP3/64)
#define WFK   1792          // wfull K (2*860 padded): 28*64
#define NCW   (WFK/64)

// ---------------- scratch ----------------
__device__ __half g_a[(size_t)NROWS * KP2];        // fp16 activations (src|dst|edge|ts)
__device__ __half g_b[(size_t)2688 * KP2];         // fp16 qkv weights (all 2580 rows, padded)
__device__ float  g_aq[(size_t)(LH + 1) * QKVN];   // anony projection (q,k cols used)
__device__ __half g_qk[(size_t)NROWS * QKNP];      // fp16 q,k
__device__ __half g_wfull[(size_t)BSZ * WFK];      // per-head weighted row sums (orig order)
__device__ __half g_wv2[(size_t)KP3 * WFK];        // head-block-diagonal Wv fp16
__device__ __half g_cm16[(size_t)BSZ * KP3];       // ctx mean fp16
__device__ __half g_relum[(size_t)BSZ * KP3];      // relu(out_proj(cm)) fp16
__device__ __half g_x16[(size_t)BSZ * KP3];        // [hl | lef] fp16
__device__ float  g_h[(size_t)BSZ * NFEAT];        // fc1 output fp32
__device__ __half g_wo16[(size_t)896 * KP3];       // out_proj_w fp16 padded
__device__ __half g_wf16[(size_t)256 * KP3];       // outfn_w fp16 padded
__device__ __half g_wfc1[(size_t)256 * KP3];       // fc1_w fp16 padded

// ---------------- helpers ----------------
__device__ __forceinline__ uint32_t smem_u32(const void* p) {
    uint32_t a;
    asm("{ .reg .u64 t; cvta.to.shared.u64 t, %1; cvt.u32.u64 %0, t; }" : "=r"(a) : "l"(p));
    return a;
}
__device__ __forceinline__ void cpa16(uint32_t s, const void* g) {
    asm volatile("cp.async.cg.shared.global [%0], [%1], 16;" :: "r"(s), "l"(g));
}
#define CP_COMMIT() asm volatile("cp.async.commit_group;" ::: "memory")
#define CP_WAIT1()  asm volatile("cp.async.wait_group 1;" ::: "memory")

#define LDSM4(r, addr) \
    asm volatile("ldmatrix.sync.aligned.m8n8.x4.shared.b16 {%0,%1,%2,%3}, [%4];" \
        : "=r"((r)[0]), "=r"((r)[1]), "=r"((r)[2]), "=r"((r)[3]) : "r"(addr) : "memory")
#define MMA_F16(acc, a, b0, b1) \
    asm volatile("mma.sync.aligned.m16n8k16.row.col.f32.f16.f16.f32 " \
        "{%0,%1,%2,%3}, {%4,%5,%6,%7}, {%8,%9}, {%0,%1,%2,%3};" \
        : "+f"((acc)[0]), "+f"((acc)[1]), "+f"((acc)[2]), "+f"((acc)[3]) \
        : "r"((a)[0]), "r"((a)[1]), "r"((a)[2]), "r"((a)[3]), "r"(b0), "r"(b1))

// fp32 Cody-Waite cos: exact reduction for our range, abs err ~4e-6.
__device__ __forceinline__ float cos_cw(float x) {
    const float c1 = 6.28125f;
    const float c2 = (float)(6.283185307179586476925286766559 - 6.28125);
    const float c3 = (float)(6.283185307179586476925286766559 - 6.28125
                             - (double)((float)(6.283185307179586476925286766559 - 6.28125)));
    float k = rintf(x * 0.15915494309189535f);
    float r = fmaf(k, -c1, x);
    r = fmaf(k, -c2, r);
    r = fmaf(k, -c3, r);
    return cosf(r);
}
__device__ __forceinline__ unsigned long long pack2(float lo, float hi) {
    unsigned long long r;
    asm("mov.b64 %0, {%1, %2};" : "=l"(r) : "f"(lo), "f"(hi));
    return r;
}
__device__ __forceinline__ void fma2(unsigned long long& d, unsigned long long a, unsigned long long b) {
    asm("fma.rn.f32x2 %0, %1, %2, %3;" : "=l"(d) : "l"(a), "l"(b), "l"(d));
}
__device__ __forceinline__ float2 unpack2(unsigned long long v) {
    float2 f;
    asm("mov.b64 {%0, %1}, %2;" : "=f"(f.x), "=f"(f.y) : "l"(v));
    return f;
}

// ---------------- K1: gather + time-encode -> fp16 A; lef -> x16 ----------------
__global__ void build_full_kernel(
    const int* __restrict__ nids, const int* __restrict__ hist_nids,
    const int* __restrict__ anon_ids, const int* __restrict__ hist_eids,
    const float* __restrict__ hist_ts, const int* __restrict__ hist_dirs,
    const float* __restrict__ node_emb, const float* __restrict__ edge_emb,
    const float* __restrict__ anony_emb, const float* __restrict__ time_w,
    const float* __restrict__ time_b, float* __restrict__ out_prevts)
{
    int row = blockIdx.x;
    int b = row / LH;
    int l = row - b * LH;
    int nid = nids[b];
    int hn  = hist_nids[row];
    int d   = hist_dirs[row];
    int src = d ? nid : hn;
    int dst = d ? hn  : nid;
    int aid = anon_ids[row];
    int eid = hist_eids[row];
    float tlast = hist_ts[b * LH + (LH - 1)];
    float dt = __fsub_rn(tlast, hist_ts[row]);
    bool last = (l == LH - 1);

    for (int j = threadIdx.x; j < KP2; j += blockDim.x) {
        float val = 0.0f;
        if (j < 172)      val = node_emb[(size_t)src * NFEAT + j];
        else if (j < 344) val = node_emb[(size_t)dst * NFEAT + (j - 172)];
        else if (j < 516) val = edge_emb[(size_t)eid * NFEAT + (j - 344)];
        else if (j < 688) {
            int jj = j - 516;
            float x = __fmul_rn(dt, time_w[jj]);
            x = __fadd_rn(x, time_b[jj]);
            val = cos_cw(x);
        }
        if (last && j < 516) {
            int xo = (j < 344) ? (NFEAT + j) : (NFEAT + j + NFEAT);
            g_x16[(size_t)b * KP3 + xo] = __float2half_rn(val);
            val = 0.0f;
        }
        g_a[(size_t)row * KP2 + j] = __float2half_rn(val);
    }
    if (last) {
        for (int j = threadIdx.x; j < NFEAT; j += blockDim.x)
            g_x16[(size_t)b * KP3 + NFEAT + 344 + j] =
                __float2half_rn(anony_emb[(size_t)aid * NFEAT + j]);
        if (threadIdx.x == 0) out_prevts[b] = tlast;
    }
}

// ---------------- K1b: in_proj_w (minus anony cols) -> padded fp16 ----------------
__global__ void split_b_kernel(const float* __restrict__ W)
{
    size_t idx = (size_t)blockIdx.x * blockDim.x + threadIdx.x;
    if (idx >= (size_t)2688 * KP2) return;
    int r = (int)(idx / KP2);
    int k = (int)(idx - (size_t)r * KP2);
    float v = 0.0f;
    if (r < QKVN) {
        if (k < 344)      v = W[(size_t)r * DIM + k];
        else if (k < 688) v = W[(size_t)r * DIM + k + NFEAT];
    }
    g_b[idx] = __float2half_rn(v);
}

// ---------------- K1c: AQ = anony_emb @ W_qk[:,344:516]^T (q,k cols only) ----------------
__global__ void anony_proj_kernel(const float* __restrict__ anony_emb,
                                  const float* __restrict__ W)
{
    int n = blockIdx.x * blockDim.x + threadIdx.x;
    int a = blockIdx.y;
    if (n >= QKN) return;
    float s = 0.0f;
    const float* wr = W + (size_t)n * DIM + 344;
    const float* ar = anony_emb + (size_t)a * NFEAT;
    #pragma unroll 4
    for (int k = 0; k < NFEAT; k++) s += ar[k] * wr[k];
    g_aq[(size_t)a * QKVN + n] = s;
}

// ---------------- K1d: generic weight -> padded fp16 converter ----------------
__global__ void conv_w_kernel(const float* __restrict__ W, __half* __restrict__ dst,
                              int nreal, int npad)
{
    size_t idx = (size_t)blockIdx.x * blockDim.x + threadIdx.x;
    if (idx >= (size_t)npad * KP3) return;
    int r = (int)(idx / KP3);
    int k = (int)(idx - (size_t)r * KP3);
    float v = (r < nreal && k < DIM) ? W[(size_t)r * DIM + k] : 0.0f;
    dst[idx] = __float2half_rn(v);
}

// ---------------- K1e: head-block-diagonal Wv -> g_wv2 [KP3 x WFK] ----------------
__global__ void conv_wv2_kernel(const float* __restrict__ W)
{
    size_t idx = (size_t)blockIdx.x * blockDim.x + threadIdx.x;
    if (idx >= (size_t)KP3 * WFK) return;
    int r = (int)(idx / WFK);
    int c = (int)(idx - (size_t)r * WFK);
    float v = 0.0f;
    if (r < DIM && c < 2 * DIM) {
        int hseg = c / DIM, cl = c - hseg * DIM;
        if (hseg == r / DHEAD)
            v = W[(size_t)(QKN + r) * DIM + cl];
    }
    g_wv2[idx] = __float2half_rn(v);
}

// ---------------- K2: q,k GEMM (R7 config, N=1720) ----------------
#define QSM_STAGE 32768
#define QSM_TOTAL (3*QSM_STAGE)

__device__ __forceinline__ void qkv_load_stage(
    uint32_t sb, int stage, int c, int bm, int bn, int tid,
    const __half* A, const __half* B)
{
    uint32_t sbase = sb + stage * QSM_STAGE;
    const size_t kof = (size_t)c * 64;
    #pragma unroll
    for (int it = 0; it < 4; it++) {
        int cid = tid + it * 256;
        int r  = cid >> 3;
        int kc = cid & 7;
        uint32_t soff = (uint32_t)(r * 128 + ((kc ^ (r & 7)) << 4));
        const char* ga = (const char*)(A + (size_t)(bm + r) * KP2 + kof) + kc * 16;
        const char* gb = (const char*)(B + (size_t)(bn + r) * KP2 + kof) + kc * 16;
        cpa16(sbase +         soff, ga);
        cpa16(sbase + 16384 + soff, gb);
    }
    CP_COMMIT();
}

__global__ __launch_bounds__(256, 2) void qkv_mma_kernel(
    const __half* __restrict__ A, const __half* __restrict__ B,
    const float* __restrict__ bias, const float* __restrict__ AQ,
    const int* __restrict__ anon_ids, __half* __restrict__ C)
{
    extern __shared__ char smem[];
    const uint32_t sb = smem_u32(smem);
    const int tid = threadIdx.x;
    const int wid = tid >> 5;
    const int lane = tid & 31;
    const int warp_m = wid >> 2;
    const int warp_n = wid & 3;
    const int bm = blockIdx.y * 128;
    const int bn = blockIdx.x * 128;

    float acc[4][4][4];
    #pragma unroll
    for (int mi = 0; mi < 4; mi++)
        #pragma unroll
        for (int nf = 0; nf < 4; nf++)
            #pragma unroll
            for (int t = 0; t < 4; t++) acc[mi][nf][t] = 0.0f;

    qkv_load_stage(sb, 0, 0, bm, bn, tid, A, B);
    qkv_load_stage(sb, 1, 1, bm, bn, tid, A, B);

    for (int c = 0; c < NC; c++) {
        const int stage = c % 3;
        CP_WAIT1();
        __syncthreads();
        if (c + 2 < NC)
            qkv_load_stage(sb, (c + 2) % 3, c + 2, bm, bn, tid, A, B);

        const uint32_t sA = sb + stage * QSM_STAGE;
        const uint32_t sB = sA + 16384;
        #pragma unroll
        for (int kk = 0; kk < 4; kk++) {
            uint32_t ah[4][4];
            #pragma unroll
            for (int mi = 0; mi < 4; mi++) {
                int mrow = warp_m * 64 + mi * 16 + (lane & 15);
                int chunk = kk * 2 + (lane >> 4);
                uint32_t addr = sA + mrow * 128 + ((chunk ^ (mrow & 7)) << 4);
                LDSM4(ah[mi], addr);
            }
            uint32_t bh[2][4];
            #pragma unroll
            for (int np = 0; np < 2; np++) {
                int nrow = warp_n * 32 + np * 16 + ((lane >> 4) << 3) + (lane & 7);
                int chunk = kk * 2 + ((lane >> 3) & 1);
                uint32_t addr = sB + nrow * 128 + ((chunk ^ (nrow & 7)) << 4);
                LDSM4(bh[np], addr);
            }
            #pragma unroll
            for (int mi = 0; mi < 4; mi++) {
                #pragma unroll
                for (int nf = 0; nf < 4; nf++) {
                    int np = nf >> 1, ri = (nf & 1) * 2;
                    MMA_F16(acc[mi][nf], ah[mi], bh[np][ri], bh[np][ri + 1]);
                }
            }
        }
    }

    const int group = lane >> 2;
    const int tc2 = (lane & 3) * 2;
    #pragma unroll
    for (int mi = 0; mi < 4; mi++) {
        int r0 = bm + warp_m * 64 + mi * 16 + group;
        int r1 = r0 + 8;
        int aid0 = anon_ids[r0];
        int aid1 = anon_ids[r1];
        bool nl0 = (r0 % LH) != (LH - 1);
        bool nl1 = (r1 % LH) != (LH - 1);
        #pragma unroll
        for (int nf = 0; nf < 4; nf++) {
            int n = bn + warp_n * 32 + nf * 8 + tc2;
            if (n >= QKN) continue;
            float2 bv = *(const float2*)(bias + n);
            float2 o0, o1;
            o0.x = acc[mi][nf][0] + bv.x;
            o0.y = acc[mi][nf][1] + bv.y;
            o1.x = acc[mi][nf][2] + bv.x;
            o1.y = acc[mi][nf][3] + bv.y;
            if (nl0) {
                float2 q = *(const float2*)(AQ + (size_t)aid0 * QKVN + n);
                o0.x += q.x; o0.y += q.y;
            }
            if (nl1) {
                float2 q = *(const float2*)(AQ + (size_t)aid1 * QKVN + n);
                o1.x += q.x; o1.y += q.y;
            }
            *(__half2*)(C + (size_t)r0 * QKNP + n) = __floats2half2_rn(o0.x, o0.y);
            *(__half2*)(C + (size_t)r1 * QKNP + n) = __floats2half2_rn(o1.x, o1.y);
        }
    }
}

// ---------------- tail fp16 MMA kernel (K_cm/K4/K5/K6) ----------------
__device__ __forceinline__ void tail_load_stage(
    uint32_t sb, int stage, int c, int bm, int bn, int tid,
    const __half* A, int akpad, const __half* B, int bkpad)
{
    uint32_t sbase = sb + stage * QSM_STAGE;
    const size_t kof = (size_t)c * 64;
    #pragma unroll
    for (int it = 0; it < 4; it++) {
        int cid = tid + it * 256;
        int r  = cid >> 3;
        int kc = cid & 7;
        uint32_t soff = (uint32_t)(r * 128 + ((kc ^ (r & 7)) << 4));
        const char* ga = (const char*)(A + (size_t)(bm + r) * akpad + kof) + kc * 16;
        const char* gb = (const char*)(B + (size_t)(bn + r) * bkpad + kof) + kc * 16;
        cpa16(sbase +         soff, ga);
        cpa16(sbase + 16384 + soff, gb);
    }
    CP_COMMIT();
}

template<bool RELU, bool F32OUT, bool F16OUT>
__global__ __launch_bounds__(256, 2) void tail_mma_kernel(
    const __half* __restrict__ A, int akpad,
    const __half* __restrict__ B, int bkpad, int nchunks,
    const float* __restrict__ bias, int nreal,
    float* __restrict__ C32, int ldc32,
    __half* __restrict__ C16, int ldc16)
{
    extern __shared__ char smem[];
    const uint32_t sb = smem_u32(smem);
    const int tid = threadIdx.x;
    const int wid = tid >> 5;
    const int lane = tid & 31;
    const int warp_m = wid >> 2;
    const int warp_n = wid & 3;
    const int bm = blockIdx.y * 128;
    const int bn = blockIdx.x * 128;

    float acc[4][4][4];
    #pragma unroll
    for (int mi = 0; mi < 4; mi++)
        #pragma unroll
        for (int nf = 0; nf < 4; nf++)
            #pragma unroll
            for (int t = 0; t < 4; t++) acc[mi][nf][t] = 0.0f;

    tail_load_stage(sb, 0, 0, bm, bn, tid, A, akpad, B, bkpad);
    tail_load_stage(sb, 1, 1, bm, bn, tid, A, akpad, B, bkpad);

    for (int c = 0; c < nchunks; c++) {
        const int stage = c % 3;
        CP_WAIT1();
        __syncthreads();
        if (c + 2 < nchunks)
            tail_load_stage(sb, (c + 2) % 3, c + 2, bm, bn, tid, A, akpad, B, bkpad);

        const uint32_t sA = sb + stage * QSM_STAGE;
        const uint32_t sB = sA + 16384;
        #pragma unroll
        for (int kk = 0; kk < 4; kk++) {
            uint32_t ah[4][4];
            #pragma unroll
            for (int mi = 0; mi < 4; mi++) {
                int mrow = warp_m * 64 + mi * 16 + (lane & 15);
                int chunk = kk * 2 + (lane >> 4);
                uint32_t addr = sA + mrow * 128 + ((chunk ^ (mrow & 7)) << 4);
                LDSM4(ah[mi], addr);
            }
            uint32_t bh[2][4];
            #pragma unroll
            for (int np = 0; np < 2; np++) {
                int nrow = warp_n * 32 + np * 16 + ((lane >> 4) << 3) + (lane & 7);
                int chunk = kk * 2 + ((lane >> 3) & 1);
                uint32_t addr = sB + nrow * 128 + ((chunk ^ (nrow & 7)) << 4);
                LDSM4(bh[np], addr);
            }
            #pragma unroll
            for (int mi = 0; mi < 4; mi++) {
                #pragma unroll
                for (int nf = 0; nf < 4; nf++) {
                    int np = nf >> 1, ri = (nf & 1) * 2;
                    MMA_F16(acc[mi][nf], ah[mi], bh[np][ri], bh[np][ri + 1]);
                }
            }
        }
    }

    const int group = lane >> 2;
    const int tc2 = (lane & 3) * 2;
    #pragma unroll
    for (int mi = 0; mi < 4; mi++) {
        int r0 = bm + warp_m * 64 + mi * 16 + group;
        int r1 = r0 + 8;
        #pragma unroll
        for (int nf = 0; nf < 4; nf++) {
            int n = bn + warp_n * 32 + nf * 8 + tc2;
            if (n >= nreal) continue;
            float2 bv = *(const float2*)(bias + n);
            float2 o0, o1;
            o0.x = acc[mi][nf][0] + bv.x;
            o0.y = acc[mi][nf][1] + bv.y;
            o1.x = acc[mi][nf][2] + bv.x;
            o1.y = acc[mi][nf][3] + bv.y;
            if (RELU) {
                o0.x = fmaxf(o0.x, 0.f); o0.y = fmaxf(o0.y, 0.f);
                o1.x = fmaxf(o1.x, 0.f); o1.y = fmaxf(o1.y, 0.f);
            }
            if (F32OUT) {
                *(float2*)(C32 + (size_t)r0 * ldc32 + n) = o0;
                *(float2*)(C32 + (size_t)r1 * ldc32 + n) = o1;
            }
            if (F16OUT) {
                *(__half2*)(C16 + (size_t)r0 * ldc16 + n) = __floats2half2_rn(o0.x, o0.y);
                *(__half2*)(C16 + (size_t)r1 * ldc16 + n) = __floats2half2_rn(o1.x, o1.y);
            }
        }
    }
}

// ---------------- SIMT f32x2 GEMM (K7 only) ----------------
#define GBM 128
#define GBN 64
#define GBK 16

__global__ __launch_bounds__(256) void gemm_nt(
    const float* __restrict__ A, int lda,
    const float* __restrict__ B, int ldb,
    const float* __restrict__ bias,
    float* __restrict__ C, int ldc,
    int M, int N, int K)
{
    __shared__ float As[GBK][GBM + 4];
    __shared__ float Bs[GBK][GBN + 4];
    const int tid = threadIdx.x;
    const int tx = tid & 15;
    const int ty = tid >> 4;
    const int bm = blockIdx.y * GBM;
    const int bn = blockIdx.x * GBN;

    unsigned long long acc[4][4];
    #pragma unroll
    for (int p = 0; p < 4; p++)
        #pragma unroll
        for (int j = 0; j < 4; j++) acc[p][j] = 0ull;

    const int lr = tid >> 2;
    const int lc = (tid & 3) * 4;

    for (int k0 = 0; k0 < K; k0 += GBK) {
        #pragma unroll
        for (int r = 0; r < 2; r++) {
            int mrow = bm + lr + r * 64;
            float4 v = make_float4(0.f, 0.f, 0.f, 0.f);
            if (mrow < M && (k0 + lc) < K)
                v = *reinterpret_cast<const float4*>(A + (size_t)mrow * lda + k0 + lc);
            As[lc + 0][lr + r * 64] = v.x; As[lc + 1][lr + r * 64] = v.y;
            As[lc + 2][lr + r * 64] = v.z; As[lc + 3][lr + r * 64] = v.w;
        }
        {
            int nrow = bn + lr;
            float4 v = make_float4(0.f, 0.f, 0.f, 0.f);
            if (nrow < N && (k0 + lc) < K)
                v = *reinterpret_cast<const float4*>(B + (size_t)nrow * ldb + k0 + lc);
            Bs[lc + 0][lr] = v.x; Bs[lc + 1][lr] = v.y;
            Bs[lc + 2][lr] = v.z; Bs[lc + 3][lr] = v.w;
        }
        __syncthreads();
        #pragma unroll
        for (int kk = 0; kk < GBK; kk++) {
            const unsigned long long* ap =
                reinterpret_cast<const unsigned long long*>(&As[kk][ty * 8]);
            unsigned long long a0 = ap[0], a1 = ap[1], a2 = ap[2], a3 = ap[3];
            const float4 bq = *reinterpret_cast<const float4*>(&Bs[kk][tx * 4]);
            unsigned long long b0 = pack2(bq.x, bq.x), b1 = pack2(bq.y, bq.y);
            unsigned long long b2 = pack2(bq.z, bq.z), b3 = pack2(bq.w, bq.w);
            fma2(acc[0][0], a0, b0); fma2(acc[0][1], a0, b1); fma2(acc[0][2], a0, b2); fma2(acc[0][3], a0, b3);
            fma2(acc[1][0], a1, b0); fma2(acc[1][1], a1, b1); fma2(acc[1][2], a1, b2); fma2(acc[1][3], a1, b3);
            fma2(acc[2][0], a2, b0); fma2(acc[2][1], a2, b1); fma2(acc[2][2], a2, b2); fma2(acc[2][3], a2, b3);
            fma2(acc[3][0], a3, b0); fma2(acc[3][1], a3, b1); fma2(acc[3][2], a3, b2); fma2(acc[3][3], a3, b3);
        }
        __syncthreads();
    }

    #pragma unroll
    for (int j = 0; j < 4; j++) {
        int n = bn + tx * 4 + j;
        if (n >= N) continue;
        float bv = bias[n];
        #pragma unroll
        for (int p = 0; p < 4; p++) {
            float2 cc = unpack2(acc[p][j]);
            int m0 = bm + ty * 8 + 2 * p;
            if (m0 < M)     C[(size_t)m0 * ldc + n] = cc.x + bv;
            if (m0 + 1 < M) C[(size_t)(m0 + 1) * ldc + n] = cc.y + bv;
        }
    }
}

// ---------------- K3: attention weights + weighted full-row sum ----------------
#define AT2 224   // half2 slots per row (215 used)
#define ATT_SMEM3 ((2*LH*AT2)*4 + (LH*LH + LH + LH + 8)*4)

__global__ __launch_bounds__(256) void attn_wfull_kernel(
    const __half* __restrict__ qk, const int* __restrict__ hist_nids,
    const int* __restrict__ anon_ids, const __half* __restrict__ a16,
    const float* __restrict__ anony_emb, __half* __restrict__ wfull)
{
    extern __shared__ char smraw[];
    __half2* sq = (__half2*)smraw;
    __half2* sk = sq + LH * AT2;
    float* sc = (float*)(sk + LH * AT2);
    float* wb = sc + LH * LH;
    int*   said = (int*)(wb + LH);

    int b = blockIdx.x;
    int h = blockIdx.y;
    int tid = threadIdx.x;
    const float scale = (float)(1.0 / sqrt(430.0));

    size_t base = (size_t)b * LH * QKNP;
    __half2 hz = __floats2half2_rn(0.f, 0.f);
    for (int idx = tid; idx < LH * AT2; idx += 256) {
        int l = idx / AT2, dp = idx - l * AT2;
        __half2 q = hz, k = hz;
        if (dp < DHEAD / 2) {
            size_t o = base + (size_t)l * QKNP + dp * 2;
            q = *(const __half2*)(qk + o + h * DHEAD);
            k = *(const __half2*)(qk + o + 860 + h * DHEAD);
        }
        sq[idx] = q; sk[idx] = k;
    }
    if (tid < LH) said[tid] = anon_ids[b * LH + tid];
    __syncthreads();

    int w = tid >> 5, lane = tid & 31;
    for (int qi = w; qi < LH; qi += 8) {
        __half2 qreg[7];
        #pragma unroll
        for (int t = 0; t < 7; t++) qreg[t] = sq[qi * AT2 + lane + 32 * t];
        for (int ki = 0; ki < LH; ki++) {
            float sx = 0.f, sy = 0.f;
            #pragma unroll
            for (int t = 0; t < 7; t++) {
                float2 qf = __half22float2(qreg[t]);
                float2 kf = __half22float2(sk[ki * AT2 + lane + 32 * t]);
                sx = fmaf(qf.x, kf.x, sx);
                sy = fmaf(qf.y, kf.y, sy);
            }
            float s = sx + sy;
            #pragma unroll
            for (int off = 16; off > 0; off >>= 1) s += __shfl_xor_sync(0xffffffffu, s, off);
            if (lane == 0) {
                int hn = hist_nids[b * LH + ki];
                bool masked = (hn == 0) && (ki != LH - 1);
                sc[qi * LH + ki] = masked ? -1e30f : s * scale;
            }
        }
    }
    __syncthreads();

    if (tid < LH) {  // softmax per query row
        int qi = tid;
        float mx = -1e30f;
        for (int ki = 0; ki < LH; ki++) mx = fmaxf(mx, sc[qi * LH + ki]);
        float sum = 0.f;
        for (int ki = 0; ki < LH; ki++) {
            float e = expf(sc[qi * LH + ki] - mx);
            sc[qi * LH + ki] = e;
            sum += e;
        }
        float inv = 1.f / sum;
        for (int ki = 0; ki < LH; ki++) sc[qi * LH + ki] *= inv;
    }
    __syncthreads();

    if (tid < LH) {  // column mean -> w
        int ki = tid;
        float s = 0.f;
        for (int qi = 0; qi < LH; qi++) s += sc[qi * LH + ki];
        wb[ki] = s * (1.0f / LH);
    }
    __syncthreads();

    // weighted full-row sum in ORIGINAL column order: src|dst|anony|edge|ts
    __half* outp = wfull + (size_t)b * WFK + (size_t)h * DIM;
    const __half* arow = a16 + (size_t)b * LH * KP2;
    for (int c = tid; c < 688; c += 256) {
        float s = 0.f;
        #pragma unroll
        for (int l = 0; l < LH; l++)
            s = fmaf(wb[l], __half2float(arow[(size_t)l * KP2 + c]), s);
        int oc = (c < 344) ? c : (c + NFEAT);   // skip anony slot
        outp[oc] = __float2half_rn(s);
    }
    for (int c = tid; c < NFEAT; c += 256) {
        float s = 0.f;
        #pragma unroll
        for (int l = 0; l < LH - 1; l++)        // last row excluded (zeroed)
            s = fmaf(wb[l], anony_emb[(size_t)said[l] * NFEAT + c], s);
        outp[344 + c] = __float2half_rn(s);
    }
}

// ---------------- host ----------------
extern "C" void kernel_launch(void* const* d_in, const int* in_sizes, int n_in,
                              void* d_out, int out_size)
{
    const int*   nids       = (const int*)  d_in[0];
    const int*   hist_nids  = (const int*)  d_in[1];
    const int*   anon_ids   = (const int*)  d_in[2];
    const int*   hist_eids  = (const int*)  d_in[3];
    const float* hist_ts    = (const float*)d_in[4];
    const int*   hist_dirs  = (const int*)  d_in[5];
    const float* node_emb   = (const float*)d_in[6];
    const float* edge_emb   = (const float*)d_in[7];
    const float* anony_emb  = (const float*)d_in[8];
    const float* time_w     = (const float*)d_in[9];
    const float* time_b     = (const float*)d_in[10];
    const float* in_proj_w  = (const float*)d_in[11];
    const float* in_proj_b  = (const float*)d_in[12];
    const float* out_proj_w = (const float*)d_in[13];
    const float* out_proj_b = (const float*)d_in[14];
    const float* outfn_w    = (const float*)d_in[15];
    const float* outfn_b    = (const float*)d_in[16];
    const float* fc1_w      = (const float*)d_in[17];
    const float* fc1_b      = (const float*)d_in[18];
    const float* fc2_w      = (const float*)d_in[19];
    const float* fc2_b      = (const float*)d_in[20];

    float* out     = (float*)d_out;
    float* out_hl  = out;
    float* out_hr  = out + (size_t)BSZ * NFEAT;
    float* out_pts = out + (size_t)2 * BSZ * NFEAT;

    __half *a16, *b16, *qk, *wfull, *wv2, *cm16, *relum, *x16, *wo16, *wf16, *wfc1;
    float *aq, *hbuf;
    cudaGetSymbolAddress((void**)&a16,   g_a);
    cudaGetSymbolAddress((void**)&b16,   g_b);
    cudaGetSymbolAddress((void**)&aq,    g_aq);
    cudaGetSymbolAddress((void**)&qk,    g_qk);
    cudaGetSymbolAddress((void**)&wfull, g_wfull);
    cudaGetSymbolAddress((void**)&wv2,   g_wv2);
    cudaGetSymbolAddress((void**)&cm16,  g_cm16);
    cudaGetSymbolAddress((void**)&relum, g_relum);
    cudaGetSymbolAddress((void**)&x16,   g_x16);
    cudaGetSymbolAddress((void**)&hbuf,  g_h);
    cudaGetSymbolAddress((void**)&wo16,  g_wo16);
    cudaGetSymbolAddress((void**)&wf16,  g_wf16);
    cudaGetSymbolAddress((void**)&wfc1,  g_wfc1);

    cudaFuncSetAttribute(attn_wfull_kernel,
                         cudaFuncAttributeMaxDynamicSharedMemorySize, ATT_SMEM3);
    cudaFuncSetAttribute(qkv_mma_kernel,
                         cudaFuncAttributeMaxDynamicSharedMemorySize, QSM_TOTAL);
    cudaFuncSetAttribute(tail_mma_kernel<false, false, true>,
                         cudaFuncAttributeMaxDynamicSharedMemorySize, QSM_TOTAL);
    cudaFuncSetAttribute(tail_mma_kernel<true, false, true>,
                         cudaFuncAttributeMaxDynamicSharedMemorySize, QSM_TOTAL);
    cudaFuncSetAttribute(tail_mma_kernel<false, true, true>,
                         cudaFuncAttributeMaxDynamicSharedMemorySize, QSM_TOTAL);
    cudaFuncSetAttribute(tail_mma_kernel<true, true, false>,
                         cudaFuncAttributeMaxDynamicSharedMemorySize, QSM_TOTAL);

    // K1 family
    build_full_kernel<<<NROWS, 128>>>(nids, hist_nids, anon_ids, hist_eids, hist_ts,
                                      hist_dirs, node_emb, edge_emb, anony_emb,
                                      time_w, time_b, out_pts);
    {
        size_t tot = (size_t)2688 * KP2;
        split_b_kernel<<<(int)((tot + 255) / 256), 256>>>(in_proj_w);
    }
    anony_proj_kernel<<<dim3((QKN + 255) / 256, LH + 1), 256>>>(anony_emb, in_proj_w);
    conv_w_kernel<<<(896 * KP3 + 255) / 256, 256>>>(out_proj_w, wo16, DIM, 896);
    conv_w_kernel<<<(256 * KP3 + 255) / 256, 256>>>(outfn_w, wf16, NFEAT, 256);
    conv_w_kernel<<<(256 * KP3 + 255) / 256, 256>>>(fc1_w, wfc1, NFEAT, 256);
    {
        size_t tot = (size_t)KP3 * WFK;
        conv_wv2_kernel<<<(int)((tot + 255) / 256), 256>>>(in_proj_w);
    }

    // K2: q,k GEMM (N=1720)
    {
        dim3 grid(QKNP / 128, NROWS / 128);
        qkv_mma_kernel<<<grid, 256, QSM_TOTAL>>>(a16, b16, in_proj_b, aq, anon_ids, qk);
    }

    // K3: attention weights + weighted full-row sums
    attn_wfull_kernel<<<dim3(BSZ, NHEAD), 256, ATT_SMEM3>>>(
        qk, hist_nids, anon_ids, a16, anony_emb, wfull);

    // K_cm: cm = wfull @ Wv2^T + bias_v   [8192 x 896, K=1792]
    tail_mma_kernel<false, false, true><<<dim3(KP3 / 128, BSZ / 128), 256, QSM_TOTAL>>>(
        wfull, WFK, wv2, WFK, NCW, in_proj_b + QKN, DIM,
        (float*)nullptr, 0, cm16, KP3);

    // K4: relum = relu(cm @ out_proj^T + b)
    tail_mma_kernel<true, false, true><<<dim3(KP3 / 128, BSZ / 128), 256, QSM_TOTAL>>>(
        cm16, KP3, wo16, KP3, NC3, out_proj_b, DIM,
        (float*)nullptr, 0, relum, KP3);

    // K5: hl = relum @ outfn^T + b -> out_hl (fp32) AND x16[:, :172]
    tail_mma_kernel<false, true, true><<<dim3(256 / 128, BSZ / 128), 256, QSM_TOTAL>>>(
        relum, KP3, wf16, KP3, NC3, outfn_b, NFEAT,
        out_hl, NFEAT, x16, KP3);

    // K6: h = relu(x16 @ fc1^T + b) -> fp32
    tail_mma_kernel<true, true, false><<<dim3(256 / 128, BSZ / 128), 256, QSM_TOTAL>>>(
        x16, KP3, wfc1, KP3, NC3, fc1_b, NFEAT,
        hbuf, NFEAT, (__half*)nullptr, 0);

    // K7: hr = h @ fc2^T + b -> out_hr (fp32 SIMT)
    {
        dim3 grid((NFEAT + GBN - 1) / GBN, BSZ / GBM);
        gemm_nt<<<grid, 256>>>(hbuf, NFEAT, fc2_w, NFEAT, fc2_b,
                               out_hr, NFEAT, BSZ, NFEAT, NFEAT);
    }
}